// round 1
// baseline (speedup 1.0000x reference)
#include <cuda_runtime.h>
#include <math.h>

#define Nn 8192
#define Ff 128
#define ALPHAv 0.2f

// scratch (device globals; no allocation allowed)
__device__ float g_h[Nn * Ff];
__device__ float g_ssrc[Nn];
__device__ float g_sdst[Nn];
__device__ float g_smax;

// ---------------------------------------------------------------------------
// K1: h = x @ W   (32 rows per block, 128 threads: thread = output column f)
// ---------------------------------------------------------------------------
__global__ void __launch_bounds__(128) k_xw(const float* __restrict__ x,
                                            const float* __restrict__ W) {
    __shared__ float xs[32 * Ff];
    int i0 = blockIdx.x * 32;
    int f = threadIdx.x;
#pragma unroll
    for (int t = 0; t < 32; ++t) xs[t * Ff + f] = x[(i0 + t) * Ff + f];
    __syncthreads();

    float acc[32];
#pragma unroll
    for (int r = 0; r < 32; ++r) acc[r] = 0.f;

    for (int k = 0; k < Ff; ++k) {
        float w = W[k * Ff + f];
#pragma unroll
        for (int r = 0; r < 32; ++r) acc[r] = fmaf(xs[r * Ff + k], w, acc[r]);
    }
#pragma unroll
    for (int r = 0; r < 32; ++r) g_h[(i0 + r) * Ff + f] = acc[r];
}

// ---------------------------------------------------------------------------
// K2: s_src[i] = h[i]·a[:128],  s_dst[i] = h[i]·a[128:]   (1 block per row)
// ---------------------------------------------------------------------------
__global__ void __launch_bounds__(128) k_scores(const float* __restrict__ a) {
    int i = blockIdx.x;
    int f = threadIdx.x;
    float hv = g_h[i * Ff + f];
    float p1 = hv * a[f];
    float p2 = hv * a[Ff + f];
#pragma unroll
    for (int o = 16; o > 0; o >>= 1) {
        p1 += __shfl_down_sync(0xffffffffu, p1, o);
        p2 += __shfl_down_sync(0xffffffffu, p2, o);
    }
    __shared__ float r1[4], r2[4];
    int w = f >> 5;
    if ((f & 31) == 0) { r1[w] = p1; r2[w] = p2; }
    __syncthreads();
    if (f == 0) {
        g_ssrc[i] = r1[0] + r1[1] + r1[2] + r1[3];
        g_sdst[i] = r2[0] + r2[1] + r2[2] + r2[3];
    }
}

// ---------------------------------------------------------------------------
// K3: global max of s_dst (deterministic tree reduction)
// ---------------------------------------------------------------------------
__global__ void __launch_bounds__(256) k_maxdst() {
    __shared__ float sm[256];
    int t = threadIdx.x;
    float m = -INFINITY;
    for (int i = t; i < Nn; i += 256) m = fmaxf(m, g_sdst[i]);
    sm[t] = m;
    __syncthreads();
#pragma unroll
    for (int s = 128; s > 0; s >>= 1) {
        if (t < s) sm[t] = fmaxf(sm[t], sm[t + s]);
        __syncthreads();
    }
    if (t == 0) g_smax = sm[0];
}

// ---------------------------------------------------------------------------
// K4: fused masked attention + P@h, single pass over adj.
//   CTA: 64 rows (i), tiles of 64 cols (j), 256 threads.
//   q_ij = adj ? exp(leaky(ssrc_i + sdst_j) - B_i) : 0,
//   B_i = leaky(ssrc_i + max_j sdst_j)  (upper bound -> q <= 1, exact softmax
//   after dividing by l_i = sum_j q_ij at the end).
// ---------------------------------------------------------------------------
__global__ void __launch_bounds__(256, 1) k_main(const int* __restrict__ adj,
                                                 float* __restrict__ out) {
    __shared__ float ps[64 * 64];   // q tile, [j][r ^ (j&31)] XOR-swizzled
    __shared__ float hs[64 * Ff];   // h tile, [j][f]

    int tid = threadIdx.x;
    int i0 = blockIdx.x * 64;
    int jj = tid & 63;      // phase-1 column within tile
    int g  = tid >> 6;      // phase-1 row group (0..3), rows r = 4k + g
    int warp = tid >> 5;
    int lane = tid & 31;
    int rb = warp * 8;      // phase-2 row base (8 rows per warp)

    float S = g_smax;
    float ssrc_r[16], B_r[16];
#pragma unroll
    for (int k = 0; k < 16; ++k) {
        int r = 4 * k + g;
        float s = g_ssrc[i0 + r];
        ssrc_r[k] = s;
        float b = s + S;
        B_r[k] = b > 0.f ? b : ALPHAv * b;
    }

    float lpart[16];
#pragma unroll
    for (int k = 0; k < 16; ++k) lpart[k] = 0.f;

    float acc[8][4];
#pragma unroll
    for (int r = 0; r < 8; ++r)
#pragma unroll
        for (int c = 0; c < 4; ++c) acc[r][c] = 0.f;

    for (int j0 = 0; j0 < Nn; j0 += 64) {
        // ---- phase 1: load h tile + compute q tile ----
        const float4* hsrc = (const float4*)(g_h + (size_t)j0 * Ff);
#pragma unroll
        for (int t = 0; t < 8; ++t)
            ((float4*)hs)[t * 256 + tid] = hsrc[t * 256 + tid];

        float sd = g_sdst[j0 + jj];
        int swz = jj & 31;
#pragma unroll
        for (int k = 0; k < 16; ++k) {
            int r = 4 * k + g;
            int av = adj[(i0 + r) * Nn + j0 + jj];
            float e = ssrc_r[k] + sd;
            e = e > 0.f ? e : ALPHAv * e;
            float q = (av > 0) ? __expf(e - B_r[k]) : 0.f;
            lpart[k] += q;
            ps[jj * 64 + (r ^ swz)] = q;
        }
        __syncthreads();

        // ---- phase 2: acc += q * h (register-tiled rank-64 update) ----
#pragma unroll 4
        for (int j = 0; j < 64; ++j) {
            int js = j & 31;
            float p[8];
#pragma unroll
            for (int r = 0; r < 8; ++r)
                p[r] = ps[j * 64 + ((rb + r) ^ js)];   // warp-uniform broadcast
            float4 hv = *(const float4*)(hs + j * Ff + lane * 4);
#pragma unroll
            for (int r = 0; r < 8; ++r) {
                acc[r][0] = fmaf(p[r], hv.x, acc[r][0]);
                acc[r][1] = fmaf(p[r], hv.y, acc[r][1]);
                acc[r][2] = fmaf(p[r], hv.z, acc[r][2]);
                acc[r][3] = fmaf(p[r], hv.w, acc[r][3]);
            }
        }
        __syncthreads();
    }

    // ---- row-sum reduction for l (reuse ps) ----
#pragma unroll
    for (int k = 0; k < 16; ++k) {
        int r = 4 * k + g;
        ps[r * 64 + jj] = lpart[k];
    }
    __syncthreads();
    float* ls = hs;  // reuse h tile buffer
    if (tid < 64) {
        float l = 0.f;
#pragma unroll 8
        for (int c = 0; c < 64; ++c)
            l += ps[tid * 64 + ((c + tid) & 63)];  // rotated -> conflict-free
        ls[tid] = 1.0f / l;
    }
    __syncthreads();

    // ---- normalize + store ----
#pragma unroll
    for (int r = 0; r < 8; ++r) {
        float il = ls[rb + r];
        float4 o;
        o.x = acc[r][0] * il;
        o.y = acc[r][1] * il;
        o.z = acc[r][2] * il;
        o.w = acc[r][3] * il;
        *(float4*)(out + (size_t)(i0 + rb + r) * Ff + lane * 4) = o;
    }
}

// ---------------------------------------------------------------------------
extern "C" void kernel_launch(void* const* d_in, const int* in_sizes, int n_in,
                              void* d_out, int out_size) {
    const float* x   = (const float*)d_in[0];
    const int*   adj = (const int*)d_in[1];
    const float* W   = (const float*)d_in[2];
    const float* a   = (const float*)d_in[3];
    float* out = (float*)d_out;

    k_xw<<<Nn / 32, 128>>>(x, W);
    k_scores<<<Nn, 128>>>(a);
    k_maxdst<<<1, 256>>>();
    k_main<<<Nn / 64, 256>>>(adj, out);
}

// round 3
// speedup vs baseline: 3.7421x; 3.7421x over previous
#include <cuda_runtime.h>
#include <cuda_fp16.h>
#include <cstdint>
#include <math.h>

#define Nn 8192
#define Ff 128
#define ALPHAv 0.2f
#define LOG2E 1.4426950408889634f

// ---- scratch (device globals; no allocation allowed) ----
__device__ __half g_hb[Nn * Ff];   // h in fp16, row-major [j][f]
__device__ float g_ssrc[Nn];       // scaled by LOG2E
__device__ float g_sdst[Nn];       // scaled by LOG2E
__device__ float g_smax;

__device__ __forceinline__ uint32_t smem_u32(const void* p) {
    uint32_t a;
    asm("{ .reg .u64 t; cvta.to.shared.u64 t, %1; cvt.u32.u64 %0, t; }"
        : "=r"(a) : "l"(p));
    return a;
}

// ---------------------------------------------------------------------------
// K1: h = x @ W  (fp32), emit fp16 h, fused s_src/s_dst scores.
// 64 rows per CTA, 256 threads.
// ---------------------------------------------------------------------------
__global__ void __launch_bounds__(256) k_xw(const float* __restrict__ x,
                                            const float* __restrict__ W,
                                            const float* __restrict__ a) {
    __shared__ __align__(16) float hsm[64 * 132];
    int tid = threadIdx.x;
    int i0 = blockIdx.x * 64;
    int f = tid & 127, rh = tid >> 7;  // rh: which 32-row half

    // stage x[64][128] (stride 132 so float4 on k stays 16B-aligned)
#pragma unroll
    for (int t = 0; t < 32; ++t)
        hsm[(rh * 32 + t) * 132 + f] = x[(size_t)(i0 + rh * 32 + t) * Ff + f];
    __syncthreads();

    float acc[32];
#pragma unroll
    for (int r = 0; r < 32; ++r) acc[r] = 0.f;

    for (int k = 0; k < Ff; k += 4) {
        float w0 = W[(k + 0) * Ff + f];
        float w1 = W[(k + 1) * Ff + f];
        float w2 = W[(k + 2) * Ff + f];
        float w3 = W[(k + 3) * Ff + f];
#pragma unroll
        for (int r = 0; r < 32; ++r) {
            float4 xv = *(const float4*)&hsm[(rh * 32 + r) * 132 + k];
            acc[r] = fmaf(xv.x, w0, acc[r]);
            acc[r] = fmaf(xv.y, w1, acc[r]);
            acc[r] = fmaf(xv.z, w2, acc[r]);
            acc[r] = fmaf(xv.w, w3, acc[r]);
        }
    }
    __syncthreads();  // xs consumed

    // write h (fp16 to gmem, fp32 to smem for scores)
#pragma unroll
    for (int r = 0; r < 32; ++r) {
        int row = rh * 32 + r;
        hsm[row * 132 + f] = acc[r];
        g_hb[(size_t)(i0 + row) * Ff + f] = __float2half(acc[r]);
    }
    __syncthreads();

    // scores: 4 threads per row
    int row = tid >> 2, c = tid & 3;
    float p1 = 0.f, p2 = 0.f;
#pragma unroll
    for (int i = 0; i < 32; ++i) {
        float hv = hsm[row * 132 + c * 32 + i];
        p1 = fmaf(hv, __ldg(a + c * 32 + i), p1);
        p2 = fmaf(hv, __ldg(a + Ff + c * 32 + i), p2);
    }
    p1 += __shfl_xor_sync(0xffffffffu, p1, 1);
    p1 += __shfl_xor_sync(0xffffffffu, p1, 2);
    p2 += __shfl_xor_sync(0xffffffffu, p2, 1);
    p2 += __shfl_xor_sync(0xffffffffu, p2, 2);
    if (c == 0) {
        g_ssrc[i0 + row] = p1 * LOG2E;
        g_sdst[i0 + row] = p2 * LOG2E;
    }
}

// ---------------------------------------------------------------------------
// K2: global max of scaled s_dst
// ---------------------------------------------------------------------------
__global__ void __launch_bounds__(256) k_maxdst() {
    __shared__ float sm[256];
    int t = threadIdx.x;
    float m = -INFINITY;
    for (int i = t; i < Nn; i += 256) m = fmaxf(m, g_sdst[i]);
    sm[t] = m;
    __syncthreads();
#pragma unroll
    for (int s = 128; s > 0; s >>= 1) {
        if (t < s) sm[t] = fmaxf(sm[t], sm[t + s]);
        __syncthreads();
    }
    if (t == 0) g_smax = sm[0];
}

// ---------------------------------------------------------------------------
// K3: fused masked softmax-numerator + HMMA GEMM (mma.sync m16n8k16 fp16)
//   CTA = 64 rows, 8 warps: warp tile m16 x n64 (4 m-slices x 2 n-slices).
//   Q split into fp16 hi+lo, computed directly in A-fragment layout.
//   H tile [j=64][f=128] fp16 in smem, chunk-XOR swizzle, double buffered.
// ---------------------------------------------------------------------------
__device__ __forceinline__ float qval(float s, float nB, float sd, int mask) {
    float t = s + sd;
    float u = t + nB;
    float v = fmaf(ALPHAv, t, nB);
    float m = fmaxf(u, v);
    float e;
    asm("ex2.approx.ftz.f32 %0, %1;" : "=f"(e) : "f"(m));
    return mask > 0 ? e : 0.f;
}

__device__ __forceinline__ void mma16816(float* d, const uint32_t* A,
                                         uint32_t b0, uint32_t b1) {
    asm volatile(
        "mma.sync.aligned.m16n8k16.row.col.f32.f16.f16.f32 "
        "{%0,%1,%2,%3}, {%4,%5,%6,%7}, {%8,%9}, {%0,%1,%2,%3};"
        : "+f"(d[0]), "+f"(d[1]), "+f"(d[2]), "+f"(d[3])
        : "r"(A[0]), "r"(A[1]), "r"(A[2]), "r"(A[3]), "r"(b0), "r"(b1));
}

__global__ void __launch_bounds__(256, 1) k_main(const int* __restrict__ adj,
                                                 float* __restrict__ out) {
    __shared__ __align__(16) char hs_raw[2 * 64 * 256];  // 2 x [64][128] fp16
    __shared__ float invl[64];
    uint32_t hs_base = smem_u32(hs_raw);

    int tid = threadIdx.x, lane = tid & 31, wid = tid >> 5;
    int ws = wid & 3, ns = wid >> 2;
    int i0 = blockIdx.x * 64;
    int g = lane >> 2, c = lane & 3;
    int rA = ws * 16 + g, rB = rA + 8;

    float S = g_smax;
    float sA = g_ssrc[i0 + rA], sB = g_ssrc[i0 + rB];
    float tA = sA + S, tB = sB + S;
    float nBA = -fmaxf(tA, ALPHAv * tA);
    float nBB = -fmaxf(tB, ALPHAv * tB);
    float lA = 0.f, lB = 0.f;

    float acc[8][4];
#pragma unroll
    for (int nb = 0; nb < 8; ++nb)
#pragma unroll
        for (int k = 0; k < 4; ++k) acc[nb][k] = 0.f;

    // H staging: thread covers rows hrow+16p, 16B chunk hchunk
    int hrow = tid >> 4, hchunk = tid & 15;
    uint32_t sts_off[4];
#pragma unroll
    for (int p = 0; p < 4; ++p) {
        int r = hrow + 16 * p;
        sts_off[p] = (uint32_t)(r * 256 + ((hchunk ^ (r & 7)) << 4));
    }
    // ldmatrix addressing components
    int lgroup = lane >> 3;
    int lrow_in = (lgroup & 1) * 8 + (lane & 7);
    int lchunk_base = ns * 8 + (lgroup >> 1);

    // preload tile 0
    uint4 hreg[4];
#pragma unroll
    for (int p = 0; p < 4; ++p)
        hreg[p] = ((const uint4*)(g_hb + (size_t)(hrow + 16 * p) * Ff))[hchunk];
#pragma unroll
    for (int p = 0; p < 4; ++p)
        *(uint4*)(hs_raw + sts_off[p]) = hreg[p];
    __syncthreads();

    for (int t = 0; t < 128; ++t) {
        int j0 = t * 64;

        // ---- A fragments: q hi/lo in fragment layout ----
        uint32_t aH[4][4], aL[4][4];
#pragma unroll
        for (int kb = 0; kb < 4; ++kb) {
            int jb = j0 + kb * 16 + 2 * c;
            const int2* pa = (const int2*)(adj + (size_t)(i0 + rA) * Nn + jb);
            const int2* pb = (const int2*)(adj + (size_t)(i0 + rB) * Nn + jb);
            int2 mA0 = __ldg(pa), mA1 = __ldg(pa + 4);
            int2 mB0 = __ldg(pb), mB1 = __ldg(pb + 4);
            float2 s0 = *(const float2*)(g_sdst + jb);
            float2 s1 = *(const float2*)(g_sdst + jb + 8);

            float qA0 = qval(sA, nBA, s0.x, mA0.x);
            float qA1 = qval(sA, nBA, s0.y, mA0.y);
            float qA2 = qval(sA, nBA, s1.x, mA1.x);
            float qA3 = qval(sA, nBA, s1.y, mA1.y);
            float qB0 = qval(sB, nBB, s0.x, mB0.x);
            float qB1 = qval(sB, nBB, s0.y, mB0.y);
            float qB2 = qval(sB, nBB, s1.x, mB1.x);
            float qB3 = qval(sB, nBB, s1.y, mB1.y);
            lA += (qA0 + qA1) + (qA2 + qA3);
            lB += (qB0 + qB1) + (qB2 + qB3);

            __half2 h0 = __floats2half2_rn(qA0, qA1);
            __half2 h1 = __floats2half2_rn(qB0, qB1);
            __half2 h2 = __floats2half2_rn(qA2, qA3);
            __half2 h3 = __floats2half2_rn(qB2, qB3);
            float2 f0 = __half22float2(h0);
            float2 f1 = __half22float2(h1);
            float2 f2 = __half22float2(h2);
            float2 f3 = __half22float2(h3);
            __half2 l0 = __floats2half2_rn(qA0 - f0.x, qA1 - f0.y);
            __half2 l1 = __floats2half2_rn(qB0 - f1.x, qB1 - f1.y);
            __half2 l2 = __floats2half2_rn(qA2 - f2.x, qA3 - f2.y);
            __half2 l3 = __floats2half2_rn(qB2 - f3.x, qB3 - f3.y);
            aH[kb][0] = *(uint32_t*)&h0;
            aH[kb][1] = *(uint32_t*)&h1;
            aH[kb][2] = *(uint32_t*)&h2;
            aH[kb][3] = *(uint32_t*)&h3;
            aL[kb][0] = *(uint32_t*)&l0;
            aL[kb][1] = *(uint32_t*)&l1;
            aL[kb][2] = *(uint32_t*)&l2;
            aL[kb][3] = *(uint32_t*)&l3;
        }

        // ---- prefetch next H tile into regs ----
        if (t < 127) {
#pragma unroll
            for (int p = 0; p < 4; ++p)
                hreg[p] = ((const uint4*)(g_hb +
                           (size_t)(j0 + 64 + hrow + 16 * p) * Ff))[hchunk];
        }

        // ---- MMA from current buffer ----
        uint32_t bufbase = hs_base + (uint32_t)((t & 1) * 16384);
#pragma unroll
        for (int kb = 0; kb < 4; ++kb) {
            int lrow = kb * 16 + lrow_in;
            uint32_t rowaddr = bufbase + (uint32_t)(lrow * 256);
            int rx = lrow & 7;
#pragma unroll
            for (int p = 0; p < 4; ++p) {
                uint32_t addr = rowaddr + (uint32_t)((((lchunk_base + 2 * p) ^ rx)) << 4);
                uint32_t b0, b1, b2, b3;
                asm volatile(
                    "ldmatrix.sync.aligned.m8n8.x4.trans.shared.b16 "
                    "{%0,%1,%2,%3}, [%4];"
                    : "=r"(b0), "=r"(b1), "=r"(b2), "=r"(b3) : "r"(addr));
                mma16816(acc[2 * p], aH[kb], b0, b1);
                mma16816(acc[2 * p], aL[kb], b0, b1);
                mma16816(acc[2 * p + 1], aH[kb], b2, b3);
                mma16816(acc[2 * p + 1], aL[kb], b2, b3);
            }
        }

        // ---- stage next H tile ----
        if (t < 127) {
            char* dst = hs_raw + ((t + 1) & 1) * 16384;
#pragma unroll
            for (int p = 0; p < 4; ++p)
                *(uint4*)(dst + sts_off[p]) = hreg[p];
        }
        __syncthreads();
    }

    // ---- row sums -> 1/l ----
    lA += __shfl_xor_sync(0xffffffffu, lA, 1);
    lA += __shfl_xor_sync(0xffffffffu, lA, 2);
    lB += __shfl_xor_sync(0xffffffffu, lB, 1);
    lB += __shfl_xor_sync(0xffffffffu, lB, 2);
    if (ns == 0 && c == 0) {
        invl[rA] = 1.0f / lA;
        invl[rB] = 1.0f / lB;
    }
    __syncthreads();

    float iA = invl[rA], iB = invl[rB];
#pragma unroll
    for (int nb = 0; nb < 8; ++nb) {
        int col = ns * 64 + nb * 8 + 2 * c;
        float2 oA, oB;
        oA.x = acc[nb][0] * iA;
        oA.y = acc[nb][1] * iA;
        oB.x = acc[nb][2] * iB;
        oB.y = acc[nb][3] * iB;
        *(float2*)(out + (size_t)(i0 + rA) * Ff + col) = oA;
        *(float2*)(out + (size_t)(i0 + rB) * Ff + col) = oB;
    }
}

// ---------------------------------------------------------------------------
extern "C" void kernel_launch(void* const* d_in, const int* in_sizes, int n_in,
                              void* d_out, int out_size) {
    const float* x   = (const float*)d_in[0];
    const int*   adj = (const int*)d_in[1];
    const float* W   = (const float*)d_in[2];
    const float* a   = (const float*)d_in[3];
    float* out = (float*)d_out;

    k_xw<<<Nn / 64, 256>>>(x, W, a);
    k_maxdst<<<1, 256>>>();
    k_main<<<Nn / 64, 256>>>(adj, out);
}

// round 4
// speedup vs baseline: 4.2232x; 1.1286x over previous
#include <cuda_runtime.h>
#include <cuda_fp16.h>
#include <cstdint>
#include <math.h>

#define Nn 8192
#define Ff 128
#define ALPHAv 0.2f
#define LOG2E 1.4426950408889634f

// ---- scratch (device globals; no allocation allowed) ----
__device__ __half g_hb[Nn * Ff];            // h in fp16, row-major [j][f]
__device__ uint32_t g_bits[Nn * Nn / 32];   // adj bitmask, [row][256 words]
__device__ float g_ssrc[Nn];                // scaled by LOG2E
__device__ float g_sdst[Nn];                // scaled by LOG2E
__device__ unsigned int g_smax_enc;         // order-monotone encoded max

__device__ __forceinline__ uint32_t smem_u32(const void* p) {
    uint32_t a;
    asm("{ .reg .u64 t; cvta.to.shared.u64 t, %1; cvt.u32.u64 %0, t; }"
        : "=r"(a) : "l"(p));
    return a;
}
__device__ __forceinline__ unsigned int enc_f(float f) {
    unsigned int b = __float_as_uint(f);
    return (b & 0x80000000u) ? ~b : (b | 0x80000000u);
}
__device__ __forceinline__ float dec_f(unsigned int u) {
    unsigned int b = (u & 0x80000000u) ? (u ^ 0x80000000u) : ~u;
    return __uint_as_float(b);
}
__device__ __forceinline__ uint32_t hexp2(uint32_t packed_h2) {
    uint32_t r;
    asm("ex2.approx.f16x2 %0, %1;" : "=r"(r) : "r"(packed_h2));
    return r;
}

// ---------------------------------------------------------------------------
// K0: init encoded max
// ---------------------------------------------------------------------------
__global__ void k_init() { g_smax_enc = 0u; }

// ---------------------------------------------------------------------------
// K_pack: adj int32 -> bitmask. 1 row per block, 8 warps, ballot.
// ---------------------------------------------------------------------------
__global__ void __launch_bounds__(256) k_pack(const int* __restrict__ adj) {
    __shared__ uint32_t wsm[256];
    int row = blockIdx.x;
    int w = threadIdx.x >> 5, lane = threadIdx.x & 31;
    const int* base = adj + (size_t)row * Nn;
#pragma unroll 4
    for (int it = 0; it < 32; ++it) {
        int word = it * 8 + w;
        int v = __ldg(base + word * 32 + lane);
        uint32_t m = __ballot_sync(0xffffffffu, v > 0);
        if (lane == 0) wsm[word] = m;
    }
    __syncthreads();
    g_bits[(size_t)row * 256 + threadIdx.x] = wsm[threadIdx.x];
}

// ---------------------------------------------------------------------------
// K1: h = x @ W (fp32, pipelined W loads), emit fp16 h + scores + smax atomic.
// ---------------------------------------------------------------------------
__global__ void __launch_bounds__(256) k_xw(const float* __restrict__ x,
                                            const float* __restrict__ W,
                                            const float* __restrict__ a) {
    __shared__ __align__(16) float hsm[64 * 132];
    int tid = threadIdx.x;
    int i0 = blockIdx.x * 64;
    int f = tid & 127, rh = tid >> 7;

#pragma unroll
    for (int t = 0; t < 32; ++t)
        hsm[(rh * 32 + t) * 132 + f] = x[(size_t)(i0 + rh * 32 + t) * Ff + f];
    __syncthreads();

    float acc[32];
#pragma unroll
    for (int r = 0; r < 32; ++r) acc[r] = 0.f;

    float w[8], wn[8];
#pragma unroll
    for (int u = 0; u < 8; ++u) w[u] = __ldg(W + u * Ff + f);

    for (int k = 0; k < Ff; k += 8) {
        if (k < Ff - 8) {
#pragma unroll
            for (int u = 0; u < 8; ++u) wn[u] = __ldg(W + (k + 8 + u) * Ff + f);
        }
#pragma unroll
        for (int r = 0; r < 32; ++r) {
            const float* xr = &hsm[(rh * 32 + r) * 132 + k];
            float4 x0 = *(const float4*)xr;
            float4 x1 = *(const float4*)(xr + 4);
            acc[r] = fmaf(x0.x, w[0], acc[r]);
            acc[r] = fmaf(x0.y, w[1], acc[r]);
            acc[r] = fmaf(x0.z, w[2], acc[r]);
            acc[r] = fmaf(x0.w, w[3], acc[r]);
            acc[r] = fmaf(x1.x, w[4], acc[r]);
            acc[r] = fmaf(x1.y, w[5], acc[r]);
            acc[r] = fmaf(x1.z, w[6], acc[r]);
            acc[r] = fmaf(x1.w, w[7], acc[r]);
        }
#pragma unroll
        for (int u = 0; u < 8; ++u) w[u] = wn[u];
    }
    __syncthreads();

#pragma unroll
    for (int r = 0; r < 32; ++r) {
        int row = rh * 32 + r;
        hsm[row * 132 + f] = acc[r];
        g_hb[(size_t)(i0 + row) * Ff + f] = __float2half(acc[r]);
    }
    __syncthreads();

    // scores: 4 threads per row
    int row = tid >> 2, c = tid & 3;
    float p1 = 0.f, p2 = 0.f;
#pragma unroll
    for (int i = 0; i < 32; ++i) {
        float hv = hsm[row * 132 + c * 32 + i];
        p1 = fmaf(hv, __ldg(a + c * 32 + i), p1);
        p2 = fmaf(hv, __ldg(a + Ff + c * 32 + i), p2);
    }
    p1 += __shfl_xor_sync(0xffffffffu, p1, 1);
    p1 += __shfl_xor_sync(0xffffffffu, p1, 2);
    p2 += __shfl_xor_sync(0xffffffffu, p2, 1);
    p2 += __shfl_xor_sync(0xffffffffu, p2, 2);
    if (c == 0) {
        float sd = p2 * LOG2E;
        g_ssrc[i0 + row] = p1 * LOG2E;
        g_sdst[i0 + row] = sd;
        atomicMax(&g_smax_enc, enc_f(sd));
    }
}

// ---------------------------------------------------------------------------
// K3: fused masked softmax-numerator + HMMA GEMM. Q fp16 (single), bitmasked.
// ---------------------------------------------------------------------------
__device__ __forceinline__ void mma16816(float* d, const uint32_t* A,
                                         uint32_t b0, uint32_t b1) {
    asm volatile(
        "mma.sync.aligned.m16n8k16.row.col.f32.f16.f16.f32 "
        "{%0,%1,%2,%3}, {%4,%5,%6,%7}, {%8,%9}, {%0,%1,%2,%3};"
        : "+f"(d[0]), "+f"(d[1]), "+f"(d[2]), "+f"(d[3])
        : "r"(A[0]), "r"(A[1]), "r"(A[2]), "r"(A[3]), "r"(b0), "r"(b1));
}

__global__ void __launch_bounds__(256, 1) k_main(float* __restrict__ out) {
    __shared__ __align__(16) char hs_raw[2 * 64 * 256];  // 2 x [64][128] fp16
    __shared__ float invl[64];
    uint32_t hs_base = smem_u32(hs_raw);

    int tid = threadIdx.x, lane = tid & 31, wid = tid >> 5;
    int ws = wid & 3, ns = wid >> 2;
    int i0 = blockIdx.x * 64;
    int g = lane >> 2, c = lane & 3;
    int rA = ws * 16 + g, rB = rA + 8;

    float S = dec_f(g_smax_enc);
    float sA = g_ssrc[i0 + rA], sB = g_ssrc[i0 + rB];
    float tA = sA + S, tB = sB + S;
    float nBA = -fmaxf(tA, ALPHAv * tA);
    float nBB = -fmaxf(tB, ALPHAv * tB);
    float lA = 0.f, lB = 0.f;

    float acc[8][4];
#pragma unroll
    for (int nb = 0; nb < 8; ++nb)
#pragma unroll
        for (int k = 0; k < 4; ++k) acc[nb][k] = 0.f;

    // H staging: thread covers rows hrow+16p, 16B chunk hchunk
    int hrow = tid >> 4, hchunk = tid & 15;
    uint32_t sts_off[4];
#pragma unroll
    for (int p = 0; p < 4; ++p) {
        int r = hrow + 16 * p;
        sts_off[p] = (uint32_t)(r * 256 + ((hchunk ^ (r & 7)) << 4));
    }
    int lgroup = lane >> 3;
    int lrow_in = (lgroup & 1) * 8 + (lane & 7);
    int lchunk_base = ns * 8 + (lgroup >> 1);

    // preload tile 0: H
    uint4 hreg[4];
#pragma unroll
    for (int p = 0; p < 4; ++p)
        hreg[p] = ((const uint4*)(g_hb + (size_t)(hrow + 16 * p) * Ff))[hchunk];
#pragma unroll
    for (int p = 0; p < 4; ++p)
        *(uint4*)(hs_raw + sts_off[p]) = hreg[p];

    // preload tile 0: masks
    const uint2* mrowA = (const uint2*)(g_bits + (size_t)(i0 + rA) * 256);
    const uint2* mrowB = (const uint2*)(g_bits + (size_t)(i0 + rB) * 256);
    uint2 mA = __ldg(mrowA), mB = __ldg(mrowB);
    __syncthreads();

    for (int t = 0; t < 128; ++t) {
        int j0 = t * 64;
        uint2 mAn, mBn;
        if (t < 127) { mAn = __ldg(mrowA + t + 1); mBn = __ldg(mrowB + t + 1); }

        // ---- A fragments: masked q in fp16 fragment layout ----
        uint32_t aH[4][4];
#pragma unroll
        for (int kb = 0; kb < 4; ++kb) {
            int jb = j0 + kb * 16 + 2 * c;
            float2 s0 = *(const float2*)(g_sdst + jb);
            float2 s1 = *(const float2*)(g_sdst + jb + 8);
            uint32_t shA = ((kb & 2) ? mA.y : mA.x) >> (((kb & 1) << 4) + 2 * c);
            uint32_t shB = ((kb & 2) ? mB.y : mB.x) >> (((kb & 1) << 4) + 2 * c);

            float t0, m0, m1, m2, m3;
            t0 = sA + s0.x; m0 = fmaxf(t0 + nBA, fmaf(ALPHAv, t0, nBA));
            t0 = sA + s0.y; m1 = fmaxf(t0 + nBA, fmaf(ALPHAv, t0, nBA));
            t0 = sA + s1.x; m2 = fmaxf(t0 + nBA, fmaf(ALPHAv, t0, nBA));
            t0 = sA + s1.y; m3 = fmaxf(t0 + nBA, fmaf(ALPHAv, t0, nBA));
            m0 = (shA & 1u) ? m0 : -64.f;
            m1 = (shA & 2u) ? m1 : -64.f;
            m2 = (shA & 0x100u) ? m2 : -64.f;
            m3 = (shA & 0x200u) ? m3 : -64.f;
            __half2 pA01 = __floats2half2_rn(m0, m1);
            __half2 pA23 = __floats2half2_rn(m2, m3);

            t0 = sB + s0.x; m0 = fmaxf(t0 + nBB, fmaf(ALPHAv, t0, nBB));
            t0 = sB + s0.y; m1 = fmaxf(t0 + nBB, fmaf(ALPHAv, t0, nBB));
            t0 = sB + s1.x; m2 = fmaxf(t0 + nBB, fmaf(ALPHAv, t0, nBB));
            t0 = sB + s1.y; m3 = fmaxf(t0 + nBB, fmaf(ALPHAv, t0, nBB));
            m0 = (shB & 1u) ? m0 : -64.f;
            m1 = (shB & 2u) ? m1 : -64.f;
            m2 = (shB & 0x100u) ? m2 : -64.f;
            m3 = (shB & 0x200u) ? m3 : -64.f;
            __half2 pB01 = __floats2half2_rn(m0, m1);
            __half2 pB23 = __floats2half2_rn(m2, m3);

            uint32_t qA01 = hexp2(*(uint32_t*)&pA01);
            uint32_t qA23 = hexp2(*(uint32_t*)&pA23);
            uint32_t qB01 = hexp2(*(uint32_t*)&pB01);
            uint32_t qB23 = hexp2(*(uint32_t*)&pB23);

            // l sums from the ROUNDED q (consistent normalization)
            float2 fa0 = __half22float2(*(__half2*)&qA01);
            float2 fa1 = __half22float2(*(__half2*)&qA23);
            float2 fb0 = __half22float2(*(__half2*)&qB01);
            float2 fb1 = __half22float2(*(__half2*)&qB23);
            lA += (fa0.x + fa0.y) + (fa1.x + fa1.y);
            lB += (fb0.x + fb0.y) + (fb1.x + fb1.y);

            aH[kb][0] = qA01;
            aH[kb][1] = qB01;
            aH[kb][2] = qA23;
            aH[kb][3] = qB23;
        }

        // ---- prefetch next H tile into regs ----
        if (t < 127) {
#pragma unroll
            for (int p = 0; p < 4; ++p)
                hreg[p] = ((const uint4*)(g_hb +
                           (size_t)(j0 + 64 + hrow + 16 * p) * Ff))[hchunk];
        }

        // ---- MMA from current buffer ----
        uint32_t bufbase = hs_base + (uint32_t)((t & 1) * 16384);
#pragma unroll
        for (int kb = 0; kb < 4; ++kb) {
            int lrow = kb * 16 + lrow_in;
            uint32_t rowaddr = bufbase + (uint32_t)(lrow * 256);
            int rx = lrow & 7;
#pragma unroll
            for (int p = 0; p < 4; ++p) {
                uint32_t addr = rowaddr + (uint32_t)((((lchunk_base + 2 * p) ^ rx)) << 4);
                uint32_t b0, b1, b2, b3;
                asm volatile(
                    "ldmatrix.sync.aligned.m8n8.x4.trans.shared.b16 "
                    "{%0,%1,%2,%3}, [%4];"
                    : "=r"(b0), "=r"(b1), "=r"(b2), "=r"(b3) : "r"(addr));
                mma16816(acc[2 * p], aH[kb], b0, b1);
                mma16816(acc[2 * p + 1], aH[kb], b2, b3);
            }
        }

        // ---- stage next H tile ----
        if (t < 127) {
            char* dst = hs_raw + ((t + 1) & 1) * 16384;
#pragma unroll
            for (int p = 0; p < 4; ++p)
                *(uint4*)(dst + sts_off[p]) = hreg[p];
        }
        mA = mAn; mB = mBn;
        __syncthreads();
    }

    // ---- row sums -> 1/l ----
    lA += __shfl_xor_sync(0xffffffffu, lA, 1);
    lA += __shfl_xor_sync(0xffffffffu, lA, 2);
    lB += __shfl_xor_sync(0xffffffffu, lB, 1);
    lB += __shfl_xor_sync(0xffffffffu, lB, 2);
    if (ns == 0 && c == 0) {
        invl[rA] = 1.0f / lA;
        invl[rB] = 1.0f / lB;
    }
    __syncthreads();

    float iA = invl[rA], iB = invl[rB];
#pragma unroll
    for (int nb = 0; nb < 8; ++nb) {
        int col = ns * 64 + nb * 8 + 2 * c;
        float2 oA, oB;
        oA.x = acc[nb][0] * iA;
        oA.y = acc[nb][1] * iA;
        oB.x = acc[nb][2] * iB;
        oB.y = acc[nb][3] * iB;
        *(float2*)(out + (size_t)(i0 + rA) * Ff + col) = oA;
        *(float2*)(out + (size_t)(i0 + rB) * Ff + col) = oB;
    }
}

// ---------------------------------------------------------------------------
extern "C" void kernel_launch(void* const* d_in, const int* in_sizes, int n_in,
                              void* d_out, int out_size) {
    const float* x   = (const float*)d_in[0];
    const int*   adj = (const int*)d_in[1];
    const float* W   = (const float*)d_in[2];
    const float* a   = (const float*)d_in[3];
    float* out = (float*)d_out;

    k_init<<<1, 1>>>();
    k_xw<<<Nn / 64, 256>>>(x, W, a);
    k_pack<<<Nn, 256>>>(adj);
    k_main<<<Nn / 64, 256>>>(out);
}

// round 5
// speedup vs baseline: 5.6821x; 1.3454x over previous
#include <cuda_runtime.h>
#include <cuda_fp16.h>
#include <cstdint>
#include <math.h>

#define Nn 8192
#define Ff 128
#define ALPHAv 0.2f
#define LOG2E 1.4426950408889634f

// ---- scratch (device globals; no allocation allowed) ----
__device__ __half g_hb[Nn * Ff];            // h in fp16, row-major [j][f]
__device__ uint32_t g_bits[Nn * Nn / 32];   // adj bitmask, [row][256 words]
__device__ float g_ssrc[Nn];                // scaled by LOG2E
__device__ float g_sdst[Nn];                // scaled by LOG2E
__device__ unsigned int g_smax_enc;         // order-monotone encoded max

__device__ __forceinline__ uint32_t smem_u32(const void* p) {
    uint32_t a;
    asm("{ .reg .u64 t; cvta.to.shared.u64 t, %1; cvt.u32.u64 %0, t; }"
        : "=r"(a) : "l"(p));
    return a;
}
__device__ __forceinline__ unsigned int enc_f(float f) {
    unsigned int b = __float_as_uint(f);
    return (b & 0x80000000u) ? ~b : (b | 0x80000000u);
}
__device__ __forceinline__ float dec_f(unsigned int u) {
    unsigned int b = (u & 0x80000000u) ? (u ^ 0x80000000u) : ~u;
    return __uint_as_float(b);
}
__device__ __forceinline__ uint32_t hexp2(uint32_t packed_h2) {
    uint32_t r;
    asm("ex2.approx.f16x2 %0, %1;" : "=r"(r) : "r"(packed_h2));
    return r;
}

// ---------------------------------------------------------------------------
__global__ void k_init() { g_smax_enc = 0u; }

// ---------------------------------------------------------------------------
// K_pack: adj int32 -> bitmask. 1 row per block, 8 warps, ballot.
// ---------------------------------------------------------------------------
__global__ void __launch_bounds__(256) k_pack(const int* __restrict__ adj) {
    __shared__ uint32_t wsm[256];
    int row = blockIdx.x;
    int w = threadIdx.x >> 5, lane = threadIdx.x & 31;
    const int* base = adj + (size_t)row * Nn;
#pragma unroll 4
    for (int it = 0; it < 32; ++it) {
        int word = it * 8 + w;
        int v = __ldg(base + word * 32 + lane);
        uint32_t m = __ballot_sync(0xffffffffu, v > 0);
        if (lane == 0) wsm[word] = m;
    }
    __syncthreads();
    g_bits[(size_t)row * 256 + threadIdx.x] = wsm[threadIdx.x];
}

// ---------------------------------------------------------------------------
// K1: h = x @ W (fp32, pipelined W loads), emit fp16 h + scores + smax atomic.
// ---------------------------------------------------------------------------
__global__ void __launch_bounds__(256) k_xw(const float* __restrict__ x,
                                            const float* __restrict__ W,
                                            const float* __restrict__ a) {
    __shared__ __align__(16) float hsm[64 * 132];
    int tid = threadIdx.x;
    int i0 = blockIdx.x * 64;
    int f = tid & 127, rh = tid >> 7;

#pragma unroll
    for (int t = 0; t < 32; ++t)
        hsm[(rh * 32 + t) * 132 + f] = x[(size_t)(i0 + rh * 32 + t) * Ff + f];
    __syncthreads();

    float acc[32];
#pragma unroll
    for (int r = 0; r < 32; ++r) acc[r] = 0.f;

    float w[8], wn[8];
#pragma unroll
    for (int u = 0; u < 8; ++u) w[u] = __ldg(W + u * Ff + f);

    for (int k = 0; k < Ff; k += 8) {
        if (k < Ff - 8) {
#pragma unroll
            for (int u = 0; u < 8; ++u) wn[u] = __ldg(W + (k + 8 + u) * Ff + f);
        }
#pragma unroll
        for (int r = 0; r < 32; ++r) {
            const float* xr = &hsm[(rh * 32 + r) * 132 + k];
            float4 x0 = *(const float4*)xr;
            float4 x1 = *(const float4*)(xr + 4);
            acc[r] = fmaf(x0.x, w[0], acc[r]);
            acc[r] = fmaf(x0.y, w[1], acc[r]);
            acc[r] = fmaf(x0.z, w[2], acc[r]);
            acc[r] = fmaf(x0.w, w[3], acc[r]);
            acc[r] = fmaf(x1.x, w[4], acc[r]);
            acc[r] = fmaf(x1.y, w[5], acc[r]);
            acc[r] = fmaf(x1.z, w[6], acc[r]);
            acc[r] = fmaf(x1.w, w[7], acc[r]);
        }
#pragma unroll
        for (int u = 0; u < 8; ++u) w[u] = wn[u];
    }
    __syncthreads();

#pragma unroll
    for (int r = 0; r < 32; ++r) {
        int row = rh * 32 + r;
        hsm[row * 132 + f] = acc[r];
        g_hb[(size_t)(i0 + row) * Ff + f] = __float2half(acc[r]);
    }
    __syncthreads();

    int row = tid >> 2, c = tid & 3;
    float p1 = 0.f, p2 = 0.f;
#pragma unroll
    for (int i = 0; i < 32; ++i) {
        float hv = hsm[row * 132 + c * 32 + i];
        p1 = fmaf(hv, __ldg(a + c * 32 + i), p1);
        p2 = fmaf(hv, __ldg(a + Ff + c * 32 + i), p2);
    }
    p1 += __shfl_xor_sync(0xffffffffu, p1, 1);
    p1 += __shfl_xor_sync(0xffffffffu, p1, 2);
    p2 += __shfl_xor_sync(0xffffffffu, p2, 1);
    p2 += __shfl_xor_sync(0xffffffffu, p2, 2);
    if (c == 0) {
        float sd = p2 * LOG2E;
        g_ssrc[i0 + row] = p1 * LOG2E;
        g_sdst[i0 + row] = sd;
        atomicMax(&g_smax_enc, enc_f(sd));
    }
}

// ---------------------------------------------------------------------------
// K_main: 512 threads, 16 warps. Q computed ONCE into smem (half2 pipeline),
// A via ldmatrix, H via cp.async double-buffer. Warp tile m16 x n32.
// ---------------------------------------------------------------------------
__device__ __forceinline__ void mma16816(float* d, const uint32_t* A,
                                         uint32_t b0, uint32_t b1) {
    asm volatile(
        "mma.sync.aligned.m16n8k16.row.col.f32.f16.f16.f32 "
        "{%0,%1,%2,%3}, {%4,%5,%6,%7}, {%8,%9}, {%0,%1,%2,%3};"
        : "+f"(d[0]), "+f"(d[1]), "+f"(d[2]), "+f"(d[3])
        : "r"(A[0]), "r"(A[1]), "r"(A[2]), "r"(A[3]), "r"(b0), "r"(b1));
}

#define QBUF_OFF 0
#define HBUF_OFF 16384
#define SDST_OFF 49152
#define INVL_OFF 65536
#define SMEM_SZ  65792

__global__ void __launch_bounds__(512, 1) k_main(float* __restrict__ out) {
    extern __shared__ __align__(16) char smem[];
    char* qbuf = smem + QBUF_OFF;
    __half* sdst_sm = (__half*)(smem + SDST_OFF);
    float* invl = (float*)(smem + INVL_OFF);
    uint32_t qb32 = smem_u32(smem + QBUF_OFF);
    uint32_t hb32 = smem_u32(smem + HBUF_OFF);

    int tid = threadIdx.x, lane = tid & 31, wid = tid >> 5;
    int ws = wid & 3, ns = wid >> 2;
    int i0 = blockIdx.x * 64;

    // ---- stage sdst fp32 -> fp16 smem ----
    {
        const float4* sp = (const float4*)g_sdst;
        uint2* dp = (uint2*)sdst_sm;
#pragma unroll
        for (int u = 0; u < 4; ++u) {
            float4 v = __ldg(sp + tid * 4 + u);
            __half2 h0 = __floats2half2_rn(v.x, v.y);
            __half2 h1 = __floats2half2_rn(v.z, v.w);
            dp[tid * 4 + u] = make_uint2(*(uint32_t*)&h0, *(uint32_t*)&h1);
        }
    }

    // ---- phase-A per-thread constants (1 row, 8 j's per thread) ----
    int qrow = tid >> 3, qc = tid & 7;
    float S = dec_f(g_smax_enc);
    float sA = g_ssrc[i0 + qrow];
    float tAx = sA + S;
    float nB = -fmaxf(tAx, ALPHAv * tAx);
    __half2 sA2 = __floats2half2_rn(sA, sA);
    __half2 nB2 = __floats2half2_rn(nB, nB);
    __half2 c02 = __floats2half2_rn(ALPHAv, ALPHAv);
    const uint32_t* mrow = g_bits + (size_t)(i0 + qrow) * 256 + (qc >> 2);
    int mshift = (qc & 3) * 8;
    uint32_t q_sts = (uint32_t)(qrow * 128 + ((qc ^ (qrow & 7)) << 4));
    float lacc = 0.f;

    // ---- H cp.async offsets (1 row, 2 chunks of 16B per thread) ----
    uint32_t h_sts0 = (uint32_t)(qrow * 256 + ((qc ^ (qrow & 7)) << 4));
    uint32_t h_sts1 = (uint32_t)(qrow * 256 + (((qc + 8) ^ (qrow & 7)) << 4));
    const char* hsrc_base = (const char*)(g_hb + (size_t)qrow * Ff) + qc * 16;

    // ---- mma addressing constants ----
    int lgroup = lane >> 3;
    int lrow_in = (lgroup & 1) * 8 + (lane & 7);
    int bchunk = ns * 4 + (lgroup >> 1);
    int arow = ws * 16 + (lane & 15);
    int arx = arow & 7;
    uint32_t a_base = (uint32_t)(arow * 128);
    int asel = lane >> 4;

    float acc[4][4];
#pragma unroll
    for (int nb = 0; nb < 4; ++nb)
#pragma unroll
        for (int k = 0; k < 4; ++k) acc[nb][k] = 0.f;

    // ---- prologue: H(0) + q(0) ----
    {
        uint32_t dst = hb32;
        const char* src = hsrc_base;
        asm volatile("cp.async.cg.shared.global [%0], [%1], 16;"
                     :: "r"(dst + h_sts0), "l"(src) : "memory");
        asm volatile("cp.async.cg.shared.global [%0], [%1], 16;"
                     :: "r"(dst + h_sts1), "l"(src + 128) : "memory");
        asm volatile("cp.async.commit_group;" ::: "memory");
    }
    __syncthreads();  // sdst visible

    for (int t = 0; t < 128; ++t) {
        // q(t) for t=0 prologue handled inside: compute q(t) at iteration t-1.
        if (t == 0) {
            // compute q(0) into buf 0
            uint32_t mw = __ldg(mrow);
            uint32_t mbyte = (mw >> mshift) & 0xFFu;
            uint4 dv = *(const uint4*)((const char*)sdst_sm + qc * 16);
            __half2* dvp = (__half2*)&dv;
            uint32_t qv[4];
#pragma unroll
            for (int p = 0; p < 4; ++p) {
                __half2 t2 = __hadd2(dvp[p], sA2);
                __half2 v2 = __hmax2(t2, __hmul2(t2, c02));
                __half2 m2 = __hadd2(v2, nB2);
                uint32_t e2 = hexp2(*(uint32_t*)&m2);
                uint32_t mk = (((mbyte >> (2 * p)) & 1u) ? 0x3C00u : 0u)
                            | (((mbyte >> (2 * p + 1)) & 1u) ? 0x3C000000u : 0u);
                __half2 q2 = __hmul2(*(__half2*)&e2, *(__half2*)&mk);
                qv[p] = *(uint32_t*)&q2;
            }
            __half2 s01 = __hadd2(*(__half2*)&qv[0], *(__half2*)&qv[1]);
            __half2 s23 = __hadd2(*(__half2*)&qv[2], *(__half2*)&qv[3]);
            __half2 sh = __hadd2(s01, s23);
            float2 fs = __half22float2(sh);
            lacc += fs.x + fs.y;
            *(uint4*)(qbuf + q_sts) = *(uint4*)qv;
            asm volatile("cp.async.wait_group 0;" ::: "memory");
            __syncthreads();  // q(0), H(0) visible
        }

        // ---- prefetch H(t+1), compute q(t+1) ----
        if (t < 127) {
            uint32_t dst = hb32 + ((t + 1) & 1) * 16384;
            const char* src = hsrc_base + (size_t)(t + 1) * 64 * 256;
            asm volatile("cp.async.cg.shared.global [%0], [%1], 16;"
                         :: "r"(dst + h_sts0), "l"(src) : "memory");
            asm volatile("cp.async.cg.shared.global [%0], [%1], 16;"
                         :: "r"(dst + h_sts1), "l"(src + 128) : "memory");
            asm volatile("cp.async.commit_group;" ::: "memory");

            int tt = t + 1;
            uint32_t mw = __ldg(mrow + 2 * tt);
            uint32_t mbyte = (mw >> mshift) & 0xFFu;
            uint4 dv = *(const uint4*)((const char*)sdst_sm + tt * 128 + qc * 16);
            __half2* dvp = (__half2*)&dv;
            uint32_t qv[4];
#pragma unroll
            for (int p = 0; p < 4; ++p) {
                __half2 t2 = __hadd2(dvp[p], sA2);
                __half2 v2 = __hmax2(t2, __hmul2(t2, c02));
                __half2 m2 = __hadd2(v2, nB2);
                uint32_t e2 = hexp2(*(uint32_t*)&m2);
                uint32_t mk = (((mbyte >> (2 * p)) & 1u) ? 0x3C00u : 0u)
                            | (((mbyte >> (2 * p + 1)) & 1u) ? 0x3C000000u : 0u);
                __half2 q2 = __hmul2(*(__half2*)&e2, *(__half2*)&mk);
                qv[p] = *(uint32_t*)&q2;
            }
            __half2 s01 = __hadd2(*(__half2*)&qv[0], *(__half2*)&qv[1]);
            __half2 s23 = __hadd2(*(__half2*)&qv[2], *(__half2*)&qv[3]);
            __half2 sh = __hadd2(s01, s23);
            float2 fs = __half22float2(sh);
            lacc += fs.x + fs.y;
            *(uint4*)(qbuf + (tt & 1) * 8192 + q_sts) = *(uint4*)qv;
        }

        // ---- MMA on tile t ----
        uint32_t qb = qb32 + (uint32_t)((t & 1) * 8192);
        uint32_t hb = hb32 + (uint32_t)((t & 1) * 16384);
#pragma unroll
        for (int kb = 0; kb < 4; ++kb) {
            uint32_t a_regs[4];
            uint32_t aaddr = qb + a_base + (uint32_t)((((2 * kb + asel) ^ arx)) << 4);
            asm volatile(
                "ldmatrix.sync.aligned.m8n8.x4.shared.b16 {%0,%1,%2,%3}, [%4];"
                : "=r"(a_regs[0]), "=r"(a_regs[1]), "=r"(a_regs[2]), "=r"(a_regs[3])
                : "r"(aaddr));
            int lrow = kb * 16 + lrow_in;
            int rx = lrow & 7;
            uint32_t rowa = hb + (uint32_t)(lrow * 256);
#pragma unroll
            for (int p = 0; p < 2; ++p) {
                uint32_t baddr = rowa + (uint32_t)((((bchunk + 2 * p) ^ rx)) << 4);
                uint32_t b0, b1, b2, b3;
                asm volatile(
                    "ldmatrix.sync.aligned.m8n8.x4.trans.shared.b16 "
                    "{%0,%1,%2,%3}, [%4];"
                    : "=r"(b0), "=r"(b1), "=r"(b2), "=r"(b3) : "r"(baddr));
                mma16816(acc[2 * p], a_regs, b0, b1);
                mma16816(acc[2 * p + 1], a_regs, b2, b3);
            }
        }

        if (t < 127)
            asm volatile("cp.async.wait_group 0;" ::: "memory");
        __syncthreads();
    }

    // ---- row sums -> 1/l (8 threads per row, adjacent lanes) ----
    lacc += __shfl_xor_sync(0xffffffffu, lacc, 1);
    lacc += __shfl_xor_sync(0xffffffffu, lacc, 2);
    lacc += __shfl_xor_sync(0xffffffffu, lacc, 4);
    if ((tid & 7) == 0) invl[qrow] = 1.0f / lacc;
    __syncthreads();

    // ---- epilogue ----
    int g = lane >> 2, c = lane & 3;
    int rA = ws * 16 + g, rB = rA + 8;
    float iA = invl[rA], iB = invl[rB];
#pragma unroll
    for (int nb = 0; nb < 4; ++nb) {
        int col = ns * 32 + nb * 8 + 2 * c;
        float2 oA, oB;
        oA.x = acc[nb][0] * iA;
        oA.y = acc[nb][1] * iA;
        oB.x = acc[nb][2] * iB;
        oB.y = acc[nb][3] * iB;
        *(float2*)(out + (size_t)(i0 + rA) * Ff + col) = oA;
        *(float2*)(out + (size_t)(i0 + rB) * Ff + col) = oB;
    }
}

// ---------------------------------------------------------------------------
extern "C" void kernel_launch(void* const* d_in, const int* in_sizes, int n_in,
                              void* d_out, int out_size) {
    const float* x   = (const float*)d_in[0];
    const int*   adj = (const int*)d_in[1];
    const float* W   = (const float*)d_in[2];
    const float* a   = (const float*)d_in[3];
    float* out = (float*)d_out;

    cudaFuncSetAttribute(k_main, cudaFuncAttributeMaxDynamicSharedMemorySize, SMEM_SZ);

    k_init<<<1, 1>>>();
    k_xw<<<Nn / 64, 256>>>(x, W, a);
    k_pack<<<Nn, 256>>>(adj);
    k_main<<<Nn / 64, 512, SMEM_SZ>>>(out);
}

// round 6
// speedup vs baseline: 6.2280x; 1.0961x over previous
#include <cuda_runtime.h>
#include <cuda_fp16.h>
#include <cstdint>
#include <math.h>

#define Nn 8192
#define Ff 128
#define ALPHAv 0.2f
#define LOG2E 1.4426950408889634f

// ---- scratch (device globals; no allocation allowed) ----
__device__ __half g_hb[Nn * Ff];            // h in fp16, row-major [j][f]
__device__ uint32_t g_bits[Nn * Nn / 32];   // adj bitmask, [row][256 words]
__device__ float g_ssrc[Nn];                // scaled by LOG2E
__device__ float g_sdst[Nn];                // scaled by LOG2E
__device__ unsigned int g_smax_enc;         // order-monotone encoded max
__device__ float g_part[2 * Nn * Ff];       // unnormalized partial outputs
__device__ float g_lpart[2 * Nn];           // partial l sums

__device__ __forceinline__ uint32_t smem_u32(const void* p) {
    uint32_t a;
    asm("{ .reg .u64 t; cvta.to.shared.u64 t, %1; cvt.u32.u64 %0, t; }"
        : "=r"(a) : "l"(p));
    return a;
}
__device__ __forceinline__ unsigned int enc_f(float f) {
    unsigned int b = __float_as_uint(f);
    return (b & 0x80000000u) ? ~b : (b | 0x80000000u);
}
__device__ __forceinline__ float dec_f(unsigned int u) {
    unsigned int b = (u & 0x80000000u) ? (u ^ 0x80000000u) : ~u;
    return __uint_as_float(b);
}
__device__ __forceinline__ uint32_t hexp2(uint32_t packed_h2) {
    uint32_t r;
    asm("ex2.approx.f16x2 %0, %1;" : "=r"(r) : "r"(packed_h2));
    return r;
}

// ---------------------------------------------------------------------------
__global__ void k_init() { g_smax_enc = 0u; }

// ---------------------------------------------------------------------------
// K_pack: adj int32 -> bitmask. 1 row per block, 8 warps, ballot.
// ---------------------------------------------------------------------------
__global__ void __launch_bounds__(256) k_pack(const int* __restrict__ adj) {
    __shared__ uint32_t wsm[256];
    int row = blockIdx.x;
    int w = threadIdx.x >> 5, lane = threadIdx.x & 31;
    const int* base = adj + (size_t)row * Nn;
#pragma unroll 4
    for (int it = 0; it < 32; ++it) {
        int word = it * 8 + w;
        int v = __ldg(base + word * 32 + lane);
        uint32_t m = __ballot_sync(0xffffffffu, v > 0);
        if (lane == 0) wsm[word] = m;
    }
    __syncthreads();
    g_bits[(size_t)row * 256 + threadIdx.x] = wsm[threadIdx.x];
}

// ---------------------------------------------------------------------------
// K1: h = x @ W, 512 threads, 64 rows/CTA. fp16 h + scores + smax atomic.
// ---------------------------------------------------------------------------
__global__ void __launch_bounds__(512) k_xw(const float* __restrict__ x,
                                            const float* __restrict__ W,
                                            const float* __restrict__ a) {
    __shared__ __align__(16) float hsm[64 * 132];
    int tid = threadIdx.x;
    int i0 = blockIdx.x * 64;
    int f = tid & 127, rq = tid >> 7;  // rq: quarter (16 rows)

#pragma unroll
    for (int t = 0; t < 16; ++t)
        hsm[(rq * 16 + t) * 132 + f] = x[(size_t)(i0 + rq * 16 + t) * Ff + f];
    __syncthreads();

    float acc[16];
#pragma unroll
    for (int r = 0; r < 16; ++r) acc[r] = 0.f;

    float w[8], wn[8];
#pragma unroll
    for (int u = 0; u < 8; ++u) w[u] = __ldg(W + u * Ff + f);

    for (int k = 0; k < Ff; k += 8) {
        if (k < Ff - 8) {
#pragma unroll
            for (int u = 0; u < 8; ++u) wn[u] = __ldg(W + (k + 8 + u) * Ff + f);
        }
#pragma unroll
        for (int r = 0; r < 16; ++r) {
            const float* xr = &hsm[(rq * 16 + r) * 132 + k];
            float4 x0 = *(const float4*)xr;
            float4 x1 = *(const float4*)(xr + 4);
            acc[r] = fmaf(x0.x, w[0], acc[r]);
            acc[r] = fmaf(x0.y, w[1], acc[r]);
            acc[r] = fmaf(x0.z, w[2], acc[r]);
            acc[r] = fmaf(x0.w, w[3], acc[r]);
            acc[r] = fmaf(x1.x, w[4], acc[r]);
            acc[r] = fmaf(x1.y, w[5], acc[r]);
            acc[r] = fmaf(x1.z, w[6], acc[r]);
            acc[r] = fmaf(x1.w, w[7], acc[r]);
        }
#pragma unroll
        for (int u = 0; u < 8; ++u) w[u] = wn[u];
    }
    __syncthreads();

#pragma unroll
    for (int r = 0; r < 16; ++r) {
        int row = rq * 16 + r;
        hsm[row * 132 + f] = acc[r];
        g_hb[(size_t)(i0 + row) * Ff + f] = __float2half(acc[r]);
    }
    __syncthreads();

    // scores: 8 threads per row, 16 features each
    int row = tid >> 3, c = tid & 7;
    float p1 = 0.f, p2 = 0.f;
#pragma unroll
    for (int i = 0; i < 16; ++i) {
        float hv = hsm[row * 132 + c * 16 + i];
        p1 = fmaf(hv, __ldg(a + c * 16 + i), p1);
        p2 = fmaf(hv, __ldg(a + Ff + c * 16 + i), p2);
    }
    p1 += __shfl_xor_sync(0xffffffffu, p1, 1);
    p1 += __shfl_xor_sync(0xffffffffu, p1, 2);
    p1 += __shfl_xor_sync(0xffffffffu, p1, 4);
    p2 += __shfl_xor_sync(0xffffffffu, p2, 1);
    p2 += __shfl_xor_sync(0xffffffffu, p2, 2);
    p2 += __shfl_xor_sync(0xffffffffu, p2, 4);
    if (c == 0) {
        float sd = p2 * LOG2E;
        g_ssrc[i0 + row] = p1 * LOG2E;
        g_sdst[i0 + row] = sd;
        atomicMax(&g_smax_enc, enc_f(sd));
    }
}

// ---------------------------------------------------------------------------
// K_main: grid 256 (128 row-groups x 2 j-halves), 256 threads, 8 warps.
// Warp tile m32 x n32 (2 m-slices x 4 n-slices). 2 CTAs/SM.
// Writes unnormalized partials + partial l.
// ---------------------------------------------------------------------------
__device__ __forceinline__ void mma16816(float* d, const uint32_t* A,
                                         uint32_t b0, uint32_t b1) {
    asm volatile(
        "mma.sync.aligned.m16n8k16.row.col.f32.f16.f16.f32 "
        "{%0,%1,%2,%3}, {%4,%5,%6,%7}, {%8,%9}, {%0,%1,%2,%3};"
        : "+f"(d[0]), "+f"(d[1]), "+f"(d[2]), "+f"(d[3])
        : "r"(A[0]), "r"(A[1]), "r"(A[2]), "r"(A[3]), "r"(b0), "r"(b1));
}

#define QBUF_OFF 0
#define HBUF_OFF 16384
#define SDST_OFF 49152
#define SMEM_SZ  57344

__global__ void __launch_bounds__(256, 2) k_main() {
    extern __shared__ __align__(16) char smem[];
    char* qbuf = smem + QBUF_OFF;
    char* sdst_sm = smem + SDST_OFF;
    uint32_t qb32 = smem_u32(smem + QBUF_OFF);
    uint32_t hb32 = smem_u32(smem + HBUF_OFF);

    int tid = threadIdx.x, lane = tid & 31, wid = tid >> 5;
    int ws = wid & 1, ns = wid >> 1;
    int bid = blockIdx.x;
    int i0 = (bid >> 1) * 64;
    int jh = bid & 1;
    int joff = jh * 4096;

    // ---- stage this half's sdst fp32 -> fp16 smem (4096 values) ----
    {
        const float4* sp = (const float4*)(g_sdst + joff);
        uint2* dp = (uint2*)sdst_sm;
#pragma unroll
        for (int u = 0; u < 4; ++u) {
            float4 v = __ldg(sp + tid * 4 + u);
            __half2 h0 = __floats2half2_rn(v.x, v.y);
            __half2 h1 = __floats2half2_rn(v.z, v.w);
            dp[tid * 4 + u] = make_uint2(*(uint32_t*)&h0, *(uint32_t*)&h1);
        }
    }

    // ---- q-compute constants: 1 row, 16 j per thread ----
    int qrow = tid >> 2, qc = tid & 3;
    float S = dec_f(g_smax_enc);
    float sA = g_ssrc[i0 + qrow];
    float tAx = sA + S;
    float nB = -fmaxf(tAx, ALPHAv * tAx);
    __half2 sA2 = __floats2half2_rn(sA, sA);
    __half2 nB2 = __floats2half2_rn(nB, nB);
    __half2 c02 = __floats2half2_rn(ALPHAv, ALPHAv);
    const uint32_t* mrow = g_bits + (size_t)(i0 + qrow) * 256 + jh * 128 + (qc >> 1);
    int mshift = (qc & 1) * 16;
    uint32_t q_sts0 = (uint32_t)(qrow * 128 + (((2 * qc) ^ (qrow & 7)) << 4));
    uint32_t q_sts1 = (uint32_t)(qrow * 128 + (((2 * qc + 1) ^ (qrow & 7)) << 4));
    float lacc = 0.f;

    // ---- H cp.async: 1 row, 4 chunks of 16B per thread ----
    int hrow = tid >> 2, hc = tid & 3;
    uint32_t h_sts[4];
#pragma unroll
    for (int u = 0; u < 4; ++u)
        h_sts[u] = (uint32_t)(hrow * 256 + (((hc * 4 + u) ^ (hrow & 7)) << 4));
    const char* hsrc_base = (const char*)g_hb + ((size_t)(joff + hrow) * Ff + hc * 32) * 2;

    // ---- mma addressing ----
    int lgroup = lane >> 3;
    int lrow_in = (lgroup & 1) * 8 + (lane & 7);
    int bchunk = ns * 4 + (lgroup >> 1);
    int arow = ws * 32 + (lane & 15);
    int arx = arow & 7;
    uint32_t a_base = (uint32_t)(arow * 128);
    int asel = lane >> 4;

    float acc[2][4][4];
#pragma unroll
    for (int mb = 0; mb < 2; ++mb)
#pragma unroll
        for (int nb = 0; nb < 4; ++nb)
#pragma unroll
            for (int k = 0; k < 4; ++k) acc[mb][nb][k] = 0.f;

    // ---- prologue: H(0) ----
#pragma unroll
    for (int u = 0; u < 4; ++u)
        asm volatile("cp.async.cg.shared.global [%0], [%1], 16;"
                     :: "r"(hb32 + h_sts[u]), "l"(hsrc_base + u * 16) : "memory");
    asm volatile("cp.async.commit_group;" ::: "memory");
    __syncthreads();  // sdst visible

    for (int t = 0; t < 64; ++t) {
        if (t == 0) {
            // compute q(0) into buf 0
            uint32_t mw = __ldg(mrow);
            uint32_t m16 = (mw >> mshift) & 0xFFFFu;
            uint4 d0 = *(const uint4*)(sdst_sm + qc * 32);
            uint4 d1 = *(const uint4*)(sdst_sm + qc * 32 + 16);
            uint32_t qv[8];
            __half2* dvp0 = (__half2*)&d0;
            __half2* dvp1 = (__half2*)&d1;
#pragma unroll
            for (int p = 0; p < 8; ++p) {
                __half2 dv = p < 4 ? dvp0[p] : dvp1[p - 4];
                __half2 t2 = __hadd2(dv, sA2);
                __half2 v2 = __hmax2(t2, __hmul2(t2, c02));
                __half2 m2 = __hadd2(v2, nB2);
                uint32_t e2 = hexp2(*(uint32_t*)&m2);
                uint32_t mk = (((m16 >> (2 * p)) & 1u) ? 0x3C00u : 0u)
                            | (((m16 >> (2 * p + 1)) & 1u) ? 0x3C000000u : 0u);
                __half2 q2 = __hmul2(*(__half2*)&e2, *(__half2*)&mk);
                qv[p] = *(uint32_t*)&q2;
            }
            __half2 sh = __hadd2(__hadd2(__hadd2(*(__half2*)&qv[0], *(__half2*)&qv[1]),
                                         __hadd2(*(__half2*)&qv[2], *(__half2*)&qv[3])),
                                 __hadd2(__hadd2(*(__half2*)&qv[4], *(__half2*)&qv[5]),
                                         __hadd2(*(__half2*)&qv[6], *(__half2*)&qv[7])));
            float2 fs = __half22float2(sh);
            lacc += fs.x + fs.y;
            *(uint4*)(qbuf + q_sts0) = *(uint4*)&qv[0];
            *(uint4*)(qbuf + q_sts1) = *(uint4*)&qv[4];
            asm volatile("cp.async.wait_group 0;" ::: "memory");
            __syncthreads();
        }

        // ---- prefetch H(t+1), compute q(t+1) ----
        if (t < 63) {
            int tt = t + 1;
            uint32_t dst = hb32 + (tt & 1) * 16384;
            const char* src = hsrc_base + (size_t)tt * 64 * 256;
#pragma unroll
            for (int u = 0; u < 4; ++u)
                asm volatile("cp.async.cg.shared.global [%0], [%1], 16;"
                             :: "r"(dst + h_sts[u]), "l"(src + u * 16) : "memory");
            asm volatile("cp.async.commit_group;" ::: "memory");

            uint32_t mw = __ldg(mrow + tt * 2);
            uint32_t m16 = (mw >> mshift) & 0xFFFFu;
            uint4 d0 = *(const uint4*)(sdst_sm + tt * 128 + qc * 32);
            uint4 d1 = *(const uint4*)(sdst_sm + tt * 128 + qc * 32 + 16);
            uint32_t qv[8];
            __half2* dvp0 = (__half2*)&d0;
            __half2* dvp1 = (__half2*)&d1;
#pragma unroll
            for (int p = 0; p < 8; ++p) {
                __half2 dv = p < 4 ? dvp0[p] : dvp1[p - 4];
                __half2 t2 = __hadd2(dv, sA2);
                __half2 v2 = __hmax2(t2, __hmul2(t2, c02));
                __half2 m2 = __hadd2(v2, nB2);
                uint32_t e2 = hexp2(*(uint32_t*)&m2);
                uint32_t mk = (((m16 >> (2 * p)) & 1u) ? 0x3C00u : 0u)
                            | (((m16 >> (2 * p + 1)) & 1u) ? 0x3C000000u : 0u);
                __half2 q2 = __hmul2(*(__half2*)&e2, *(__half2*)&mk);
                qv[p] = *(uint32_t*)&q2;
            }
            __half2 sh = __hadd2(__hadd2(__hadd2(*(__half2*)&qv[0], *(__half2*)&qv[1]),
                                         __hadd2(*(__half2*)&qv[2], *(__half2*)&qv[3])),
                                 __hadd2(__hadd2(*(__half2*)&qv[4], *(__half2*)&qv[5]),
                                         __hadd2(*(__half2*)&qv[6], *(__half2*)&qv[7])));
            float2 fs = __half22float2(sh);
            lacc += fs.x + fs.y;
            char* qd = qbuf + (tt & 1) * 8192;
            *(uint4*)(qd + q_sts0) = *(uint4*)&qv[0];
            *(uint4*)(qd + q_sts1) = *(uint4*)&qv[4];
        }

        // ---- MMA on tile t ----
        uint32_t qb = qb32 + (uint32_t)((t & 1) * 8192);
        uint32_t hb = hb32 + (uint32_t)((t & 1) * 16384);
#pragma unroll
        for (int kb = 0; kb < 4; ++kb) {
            uint32_t a0[4], a1[4];
            uint32_t aaddr = qb + a_base + (uint32_t)((((2 * kb + asel) ^ arx)) << 4);
            asm volatile(
                "ldmatrix.sync.aligned.m8n8.x4.shared.b16 {%0,%1,%2,%3}, [%4];"
                : "=r"(a0[0]), "=r"(a0[1]), "=r"(a0[2]), "=r"(a0[3]) : "r"(aaddr));
            asm volatile(
                "ldmatrix.sync.aligned.m8n8.x4.shared.b16 {%0,%1,%2,%3}, [%4];"
                : "=r"(a1[0]), "=r"(a1[1]), "=r"(a1[2]), "=r"(a1[3])
                : "r"(aaddr + 2048));
            int lrow = kb * 16 + lrow_in;
            int rx = lrow & 7;
            uint32_t rowa = hb + (uint32_t)(lrow * 256);
#pragma unroll
            for (int p = 0; p < 2; ++p) {
                uint32_t baddr = rowa + (uint32_t)((((bchunk + 2 * p) ^ rx)) << 4);
                uint32_t b0, b1, b2, b3;
                asm volatile(
                    "ldmatrix.sync.aligned.m8n8.x4.trans.shared.b16 "
                    "{%0,%1,%2,%3}, [%4];"
                    : "=r"(b0), "=r"(b1), "=r"(b2), "=r"(b3) : "r"(baddr));
                mma16816(acc[0][2 * p], a0, b0, b1);
                mma16816(acc[0][2 * p + 1], a0, b2, b3);
                mma16816(acc[1][2 * p], a1, b0, b1);
                mma16816(acc[1][2 * p + 1], a1, b2, b3);
            }
        }

        if (t < 63)
            asm volatile("cp.async.wait_group 0;" ::: "memory");
        __syncthreads();
    }

    // ---- partial l (4 threads per row) ----
    lacc += __shfl_xor_sync(0xffffffffu, lacc, 1);
    lacc += __shfl_xor_sync(0xffffffffu, lacc, 2);
    if (qc == 0) g_lpart[jh * Nn + i0 + qrow] = lacc;

    // ---- write unnormalized partials ----
    int g = lane >> 2, c = lane & 3;
    float* pb = g_part + (size_t)jh * Nn * Ff;
#pragma unroll
    for (int mb = 0; mb < 2; ++mb) {
        int rA = ws * 32 + mb * 16 + g, rB = rA + 8;
#pragma unroll
        for (int nb = 0; nb < 4; ++nb) {
            int col = ns * 32 + nb * 8 + 2 * c;
            *(float2*)(pb + (size_t)(i0 + rA) * Ff + col) =
                make_float2(acc[mb][nb][0], acc[mb][nb][1]);
            *(float2*)(pb + (size_t)(i0 + rB) * Ff + col) =
                make_float2(acc[mb][nb][2], acc[mb][nb][3]);
        }
    }
}

// ---------------------------------------------------------------------------
// K_combine: out = (p0 + p1) / (l0 + l1)
// ---------------------------------------------------------------------------
__global__ void __launch_bounds__(256) k_combine(float* __restrict__ out) {
    int idx = blockIdx.x * 256 + threadIdx.x;
    int row = idx >> 7;
    float l = g_lpart[row] + g_lpart[Nn + row];
    out[idx] = (g_part[idx] + g_part[Nn * Ff + idx]) * (1.0f / l);
}

// ---------------------------------------------------------------------------
extern "C" void kernel_launch(void* const* d_in, const int* in_sizes, int n_in,
                              void* d_out, int out_size) {
    const float* x   = (const float*)d_in[0];
    const int*   adj = (const int*)d_in[1];
    const float* W   = (const float*)d_in[2];
    const float* a   = (const float*)d_in[3];
    float* out = (float*)d_out;

    cudaFuncSetAttribute(k_main, cudaFuncAttributeMaxDynamicSharedMemorySize, SMEM_SZ);

    k_init<<<1, 1>>>();
    k_xw<<<Nn / 64, 512>>>(x, W, a);
    k_pack<<<Nn, 256>>>(adj);
    k_main<<<Nn / 64 * 2, 256, SMEM_SZ>>>();
    k_combine<<<Nn * Ff / 256, 256>>>(out);
}

// round 7
// speedup vs baseline: 7.3717x; 1.1836x over previous
#include <cuda_runtime.h>
#include <cuda_fp16.h>
#include <cstdint>
#include <math.h>

#define Nn 8192
#define Ff 128
#define ALPHAv 0.2f
#define LOG2E 1.4426950408889634f

// ---- scratch (device globals; no allocation allowed) ----
__device__ __half g_hb[Nn * Ff];            // h in fp16, row-major [j][f]
__device__ float g_ssrc[Nn];                // scaled by LOG2E
__device__ float g_sdst[Nn];                // scaled by LOG2E
__device__ unsigned int g_smax_enc;         // order-monotone encoded max
__device__ float g_part[2 * Nn * Ff];       // unnormalized partial outputs
__device__ float g_lpart[2 * Nn];           // partial l sums

__device__ __forceinline__ uint32_t smem_u32(const void* p) {
    uint32_t a;
    asm("{ .reg .u64 t; cvta.to.shared.u64 t, %1; cvt.u32.u64 %0, t; }"
        : "=r"(a) : "l"(p));
    return a;
}
__device__ __forceinline__ unsigned int enc_f(float f) {
    unsigned int b = __float_as_uint(f);
    return (b & 0x80000000u) ? ~b : (b | 0x80000000u);
}
__device__ __forceinline__ float dec_f(unsigned int u) {
    unsigned int b = (u & 0x80000000u) ? (u ^ 0x80000000u) : ~u;
    return __uint_as_float(b);
}
__device__ __forceinline__ uint32_t hexp2(uint32_t packed_h2) {
    uint32_t r;
    asm("ex2.approx.f16x2 %0, %1;" : "=r"(r) : "r"(packed_h2));
    return r;
}

// ---------------------------------------------------------------------------
__global__ void k_init() { g_smax_enc = 0u; }

// ---------------------------------------------------------------------------
// K1: h = x @ W, 512 threads, 64 rows/CTA. fp16 h + scores + smax atomic.
// ---------------------------------------------------------------------------
__global__ void __launch_bounds__(512) k_xw(const float* __restrict__ x,
                                            const float* __restrict__ W,
                                            const float* __restrict__ a) {
    __shared__ __align__(16) float hsm[64 * 132];
    int tid = threadIdx.x;
    int i0 = blockIdx.x * 64;
    int f = tid & 127, rq = tid >> 7;  // rq: quarter (16 rows)

#pragma unroll
    for (int t = 0; t < 16; ++t)
        hsm[(rq * 16 + t) * 132 + f] = x[(size_t)(i0 + rq * 16 + t) * Ff + f];
    __syncthreads();

    float acc[16];
#pragma unroll
    for (int r = 0; r < 16; ++r) acc[r] = 0.f;

    float w[8], wn[8];
#pragma unroll
    for (int u = 0; u < 8; ++u) w[u] = __ldg(W + u * Ff + f);

    for (int k = 0; k < Ff; k += 8) {
        if (k < Ff - 8) {
#pragma unroll
            for (int u = 0; u < 8; ++u) wn[u] = __ldg(W + (k + 8 + u) * Ff + f);
        }
#pragma unroll
        for (int r = 0; r < 16; ++r) {
            const float* xr = &hsm[(rq * 16 + r) * 132 + k];
            float4 x0 = *(const float4*)xr;
            float4 x1 = *(const float4*)(xr + 4);
            acc[r] = fmaf(x0.x, w[0], acc[r]);
            acc[r] = fmaf(x0.y, w[1], acc[r]);
            acc[r] = fmaf(x0.z, w[2], acc[r]);
            acc[r] = fmaf(x0.w, w[3], acc[r]);
            acc[r] = fmaf(x1.x, w[4], acc[r]);
            acc[r] = fmaf(x1.y, w[5], acc[r]);
            acc[r] = fmaf(x1.z, w[6], acc[r]);
            acc[r] = fmaf(x1.w, w[7], acc[r]);
        }
#pragma unroll
        for (int u = 0; u < 8; ++u) w[u] = wn[u];
    }
    __syncthreads();

#pragma unroll
    for (int r = 0; r < 16; ++r) {
        int row = rq * 16 + r;
        hsm[row * 132 + f] = acc[r];
        g_hb[(size_t)(i0 + row) * Ff + f] = __float2half(acc[r]);
    }
    __syncthreads();

    // scores: 8 threads per row, 16 features each
    int row = tid >> 3, c = tid & 7;
    float p1 = 0.f, p2 = 0.f;
#pragma unroll
    for (int i = 0; i < 16; ++i) {
        float hv = hsm[row * 132 + c * 16 + i];
        p1 = fmaf(hv, __ldg(a + c * 16 + i), p1);
        p2 = fmaf(hv, __ldg(a + Ff + c * 16 + i), p2);
    }
    p1 += __shfl_xor_sync(0xffffffffu, p1, 1);
    p1 += __shfl_xor_sync(0xffffffffu, p1, 2);
    p1 += __shfl_xor_sync(0xffffffffu, p1, 4);
    p2 += __shfl_xor_sync(0xffffffffu, p2, 1);
    p2 += __shfl_xor_sync(0xffffffffu, p2, 2);
    p2 += __shfl_xor_sync(0xffffffffu, p2, 4);
    if (c == 0) {
        float sd = p2 * LOG2E;
        g_ssrc[i0 + row] = p1 * LOG2E;
        g_sdst[i0 + row] = sd;
        atomicMax(&g_smax_enc, enc_f(sd));
    }
}

// ---------------------------------------------------------------------------
// K_main: grid 256 (128 row-groups x 2 j-halves), 256 threads, 8 warps.
// Warp tile m32 x n32. Reads adj DIRECTLY (no pre-pack pass); adj LDGs for
// tile t+1 issue before MMA(t) so their latency hides under tensor work.
// ---------------------------------------------------------------------------
__device__ __forceinline__ void mma16816(float* d, const uint32_t* A,
                                         uint32_t b0, uint32_t b1) {
    asm volatile(
        "mma.sync.aligned.m16n8k16.row.col.f32.f16.f16.f32 "
        "{%0,%1,%2,%3}, {%4,%5,%6,%7}, {%8,%9}, {%0,%1,%2,%3};"
        : "+f"(d[0]), "+f"(d[1]), "+f"(d[2]), "+f"(d[3])
        : "r"(A[0]), "r"(A[1]), "r"(A[2]), "r"(A[3]), "r"(b0), "r"(b1));
}

// compute 16 masked q (fp16) for tile tt from preloaded adj ints; STS; return l
__device__ __forceinline__ float q_emit(const int* ai, const char* sdst_sm,
                                        int tt, int qc,
                                        __half2 sA2, __half2 nB2, __half2 c02,
                                        char* qdst, uint32_t q_sts0, uint32_t q_sts1) {
    uint4 d0 = *(const uint4*)(sdst_sm + tt * 128 + qc * 32);
    uint4 d1 = *(const uint4*)(sdst_sm + tt * 128 + qc * 32 + 16);
    uint32_t qv[8];
    __half2* dvp0 = (__half2*)&d0;
    __half2* dvp1 = (__half2*)&d1;
#pragma unroll
    for (int p = 0; p < 8; ++p) {
        __half2 dv = p < 4 ? dvp0[p] : dvp1[p - 4];
        __half2 t2 = __hadd2(dv, sA2);
        __half2 v2 = __hmax2(t2, __hmul2(t2, c02));
        __half2 m2 = __hadd2(v2, nB2);
        uint32_t e2 = hexp2(*(uint32_t*)&m2);
        uint32_t mk = (ai[2 * p] > 0 ? 0x3C00u : 0u)
                    | (ai[2 * p + 1] > 0 ? 0x3C000000u : 0u);
        __half2 q2 = __hmul2(*(__half2*)&e2, *(__half2*)&mk);
        qv[p] = *(uint32_t*)&q2;
    }
    __half2 sh = __hadd2(__hadd2(__hadd2(*(__half2*)&qv[0], *(__half2*)&qv[1]),
                                 __hadd2(*(__half2*)&qv[2], *(__half2*)&qv[3])),
                         __hadd2(__hadd2(*(__half2*)&qv[4], *(__half2*)&qv[5]),
                                 __hadd2(*(__half2*)&qv[6], *(__half2*)&qv[7])));
    float2 fs = __half22float2(sh);
    *(uint4*)(qdst + q_sts0) = *(uint4*)&qv[0];
    *(uint4*)(qdst + q_sts1) = *(uint4*)&qv[4];
    return fs.x + fs.y;
}

#define QBUF_OFF 0
#define HBUF_OFF 16384
#define SDST_OFF 49152
#define SMEM_SZ  57344

__global__ void __launch_bounds__(256, 2) k_main(const int* __restrict__ adj) {
    extern __shared__ __align__(16) char smem[];
    char* qbuf = smem + QBUF_OFF;
    char* sdst_sm = smem + SDST_OFF;
    uint32_t qb32 = smem_u32(smem + QBUF_OFF);
    uint32_t hb32 = smem_u32(smem + HBUF_OFF);

    int tid = threadIdx.x, lane = tid & 31, wid = tid >> 5;
    int ws = wid & 1, ns = wid >> 1;
    int bid = blockIdx.x;
    int i0 = (bid >> 1) * 64;
    int jh = bid & 1;
    int joff = jh * 4096;

    // ---- stage this half's sdst fp32 -> fp16 smem (4096 values) ----
    {
        const float4* sp = (const float4*)(g_sdst + joff);
        uint2* dp = (uint2*)sdst_sm;
#pragma unroll
        for (int u = 0; u < 4; ++u) {
            float4 v = __ldg(sp + tid * 4 + u);
            __half2 h0 = __floats2half2_rn(v.x, v.y);
            __half2 h1 = __floats2half2_rn(v.z, v.w);
            dp[tid * 4 + u] = make_uint2(*(uint32_t*)&h0, *(uint32_t*)&h1);
        }
    }

    // ---- q-compute constants: 1 row, 16 j per thread ----
    int qrow = tid >> 2, qc = tid & 3;
    float S = dec_f(g_smax_enc);
    float sA = g_ssrc[i0 + qrow];
    float tAx = sA + S;
    float nB = -fmaxf(tAx, ALPHAv * tAx);
    __half2 sA2 = __floats2half2_rn(sA, sA);
    __half2 nB2 = __floats2half2_rn(nB, nB);
    __half2 c02 = __floats2half2_rn(ALPHAv, ALPHAv);
    const int4* arow_p = (const int4*)(adj + (size_t)(i0 + qrow) * Nn + joff + qc * 16);
    uint32_t q_sts0 = (uint32_t)(qrow * 128 + (((2 * qc) ^ (qrow & 7)) << 4));
    uint32_t q_sts1 = (uint32_t)(qrow * 128 + (((2 * qc + 1) ^ (qrow & 7)) << 4));
    float lacc = 0.f;

    // ---- H cp.async: 1 row, 4 chunks of 16B per thread ----
    int hrow = tid >> 2, hc = tid & 3;
    uint32_t h_sts[4];
#pragma unroll
    for (int u = 0; u < 4; ++u)
        h_sts[u] = (uint32_t)(hrow * 256 + (((hc * 4 + u) ^ (hrow & 7)) << 4));
    const char* hsrc_base = (const char*)g_hb + ((size_t)(joff + hrow) * Ff + hc * 32) * 2;

    // ---- mma addressing ----
    int lgroup = lane >> 3;
    int lrow_in = (lgroup & 1) * 8 + (lane & 7);
    int bchunk = ns * 4 + (lgroup >> 1);
    int arow = ws * 32 + (lane & 15);
    int arx = arow & 7;
    uint32_t a_base = (uint32_t)(arow * 128);
    int asel = lane >> 4;

    float acc[2][4][4];
#pragma unroll
    for (int mb = 0; mb < 2; ++mb)
#pragma unroll
        for (int nb = 0; nb < 4; ++nb)
#pragma unroll
            for (int k = 0; k < 4; ++k) acc[mb][nb][k] = 0.f;

    // ---- prologue: H(0) cp.async + adj(0) ----
#pragma unroll
    for (int u = 0; u < 4; ++u)
        asm volatile("cp.async.cg.shared.global [%0], [%1], 16;"
                     :: "r"(hb32 + h_sts[u]), "l"(hsrc_base + u * 16) : "memory");
    asm volatile("cp.async.commit_group;" ::: "memory");

    int4 av[4];
#pragma unroll
    for (int u = 0; u < 4; ++u) av[u] = __ldg(arow_p + u);
    __syncthreads();  // sdst visible

    // q(0)
    lacc += q_emit((const int*)av, sdst_sm, 0, qc, sA2, nB2, c02,
                   qbuf, q_sts0, q_sts1);
    asm volatile("cp.async.wait_group 0;" ::: "memory");
    __syncthreads();  // q(0), H(0) visible

    for (int t = 0; t < 64; ++t) {
        // ---- issue H(t+1) cp.async + adj(t+1) LDGs (latency hides under MMA) ----
        if (t < 63) {
            int tt = t + 1;
            uint32_t dst = hb32 + (tt & 1) * 16384;
            const char* src = hsrc_base + (size_t)tt * 64 * 256;
#pragma unroll
            for (int u = 0; u < 4; ++u)
                asm volatile("cp.async.cg.shared.global [%0], [%1], 16;"
                             :: "r"(dst + h_sts[u]), "l"(src + u * 16) : "memory");
            asm volatile("cp.async.commit_group;" ::: "memory");
#pragma unroll
            for (int u = 0; u < 4; ++u) av[u] = __ldg(arow_p + t * 16 + 16 + u);
        }

        // ---- MMA on tile t ----
        uint32_t qb = qb32 + (uint32_t)((t & 1) * 8192);
        uint32_t hb = hb32 + (uint32_t)((t & 1) * 16384);
#pragma unroll
        for (int kb = 0; kb < 4; ++kb) {
            uint32_t a0[4], a1[4];
            uint32_t aaddr = qb + a_base + (uint32_t)((((2 * kb + asel) ^ arx)) << 4);
            asm volatile(
                "ldmatrix.sync.aligned.m8n8.x4.shared.b16 {%0,%1,%2,%3}, [%4];"
                : "=r"(a0[0]), "=r"(a0[1]), "=r"(a0[2]), "=r"(a0[3]) : "r"(aaddr));
            asm volatile(
                "ldmatrix.sync.aligned.m8n8.x4.shared.b16 {%0,%1,%2,%3}, [%4];"
                : "=r"(a1[0]), "=r"(a1[1]), "=r"(a1[2]), "=r"(a1[3])
                : "r"(aaddr + 2048));
            int lrow = kb * 16 + lrow_in;
            int rx = lrow & 7;
            uint32_t rowa = hb + (uint32_t)(lrow * 256);
#pragma unroll
            for (int p = 0; p < 2; ++p) {
                uint32_t baddr = rowa + (uint32_t)((((bchunk + 2 * p) ^ rx)) << 4);
                uint32_t b0, b1, b2, b3;
                asm volatile(
                    "ldmatrix.sync.aligned.m8n8.x4.trans.shared.b16 "
                    "{%0,%1,%2,%3}, [%4];"
                    : "=r"(b0), "=r"(b1), "=r"(b2), "=r"(b3) : "r"(baddr));
                mma16816(acc[0][2 * p], a0, b0, b1);
                mma16816(acc[0][2 * p + 1], a0, b2, b3);
                mma16816(acc[1][2 * p], a1, b0, b1);
                mma16816(acc[1][2 * p + 1], a1, b2, b3);
            }
        }

        // ---- compute q(t+1) from prefetched adj, STS into other buffer ----
        if (t < 63) {
            int tt = t + 1;
            lacc += q_emit((const int*)av, sdst_sm, tt, qc, sA2, nB2, c02,
                           qbuf + (tt & 1) * 8192, q_sts0, q_sts1);
            asm volatile("cp.async.wait_group 0;" ::: "memory");
        }
        __syncthreads();
    }

    // ---- partial l (4 threads per row) ----
    lacc += __shfl_xor_sync(0xffffffffu, lacc, 1);
    lacc += __shfl_xor_sync(0xffffffffu, lacc, 2);
    if (qc == 0) g_lpart[jh * Nn + i0 + qrow] = lacc;

    // ---- write unnormalized partials ----
    int g = lane >> 2, c = lane & 3;
    float* pb = g_part + (size_t)jh * Nn * Ff;
#pragma unroll
    for (int mb = 0; mb < 2; ++mb) {
        int rA = ws * 32 + mb * 16 + g, rB = rA + 8;
#pragma unroll
        for (int nb = 0; nb < 4; ++nb) {
            int col = ns * 32 + nb * 8 + 2 * c;
            *(float2*)(pb + (size_t)(i0 + rA) * Ff + col) =
                make_float2(acc[mb][nb][0], acc[mb][nb][1]);
            *(float2*)(pb + (size_t)(i0 + rB) * Ff + col) =
                make_float2(acc[mb][nb][2], acc[mb][nb][3]);
        }
    }
}

// ---------------------------------------------------------------------------
// K_combine: out = (p0 + p1) / (l0 + l1)
// ---------------------------------------------------------------------------
__global__ void __launch_bounds__(256) k_combine(float* __restrict__ out) {
    int idx = blockIdx.x * 256 + threadIdx.x;
    int row = idx >> 7;
    float l = g_lpart[row] + g_lpart[Nn + row];
    out[idx] = (g_part[idx] + g_part[Nn * Ff + idx]) * (1.0f / l);
}

// ---------------------------------------------------------------------------
extern "C" void kernel_launch(void* const* d_in, const int* in_sizes, int n_in,
                              void* d_out, int out_size) {
    const float* x   = (const float*)d_in[0];
    const int*   adj = (const int*)d_in[1];
    const float* W   = (const float*)d_in[2];
    const float* a   = (const float*)d_in[3];
    float* out = (float*)d_out;

    cudaFuncSetAttribute(k_main, cudaFuncAttributeMaxDynamicSharedMemorySize, SMEM_SZ);

    k_init<<<1, 1>>>();
    k_xw<<<Nn / 64, 512>>>(x, W, a);
    k_main<<<Nn / 64 * 2, 256, SMEM_SZ>>>(adj);
    k_combine<<<Nn * Ff / 256, 256>>>(out);
}

// round 8
// speedup vs baseline: 7.5747x; 1.0275x over previous
#include <cuda_runtime.h>
#include <cuda_fp16.h>
#include <cstdint>
#include <math.h>

#define Nn 8192
#define Ff 128
#define ALPHAv 0.2f
#define LOG2E 1.4426950408889634f

// ---- scratch (device globals; no allocation allowed) ----
__device__ __half g_hb[Nn * Ff];            // h in fp16, row-major [j][f]
__device__ float g_ssrc[Nn];                // scaled by LOG2E
__device__ float g_sdst[Nn];                // scaled by LOG2E
__device__ unsigned int g_smax_enc;         // order-monotone encoded max
__device__ float g_part[2 * Nn * Ff];       // unnormalized partial outputs
__device__ float g_lpart[2 * Nn];           // partial l sums

__device__ __forceinline__ uint32_t smem_u32(const void* p) {
    uint32_t a;
    asm("{ .reg .u64 t; cvta.to.shared.u64 t, %1; cvt.u32.u64 %0, t; }"
        : "=r"(a) : "l"(p));
    return a;
}
__device__ __forceinline__ unsigned int enc_f(float f) {
    unsigned int b = __float_as_uint(f);
    return (b & 0x80000000u) ? ~b : (b | 0x80000000u);
}
__device__ __forceinline__ float dec_f(unsigned int u) {
    unsigned int b = (u & 0x80000000u) ? (u ^ 0x80000000u) : ~u;
    return __uint_as_float(b);
}
__device__ __forceinline__ uint32_t hexp2(uint32_t packed_h2) {
    uint32_t r;
    asm("ex2.approx.f16x2 %0, %1;" : "=r"(r) : "r"(packed_h2));
    return r;
}

// ---------------------------------------------------------------------------
__global__ void k_init() { g_smax_enc = 0u; }

// ---------------------------------------------------------------------------
// K1: h = x @ W, 512 threads, 64 rows/CTA. fp16 h + scores + smax atomic.
// ---------------------------------------------------------------------------
__global__ void __launch_bounds__(512) k_xw(const float* __restrict__ x,
                                            const float* __restrict__ W,
                                            const float* __restrict__ a) {
    __shared__ __align__(16) float hsm[64 * 132];
    int tid = threadIdx.x;
    int i0 = blockIdx.x * 64;
    int f = tid & 127, rq = tid >> 7;

#pragma unroll
    for (int t = 0; t < 16; ++t)
        hsm[(rq * 16 + t) * 132 + f] = x[(size_t)(i0 + rq * 16 + t) * Ff + f];
    __syncthreads();

    float acc[16];
#pragma unroll
    for (int r = 0; r < 16; ++r) acc[r] = 0.f;

    float w[8], wn[8];
#pragma unroll
    for (int u = 0; u < 8; ++u) w[u] = __ldg(W + u * Ff + f);

    for (int k = 0; k < Ff; k += 8) {
        if (k < Ff - 8) {
#pragma unroll
            for (int u = 0; u < 8; ++u) wn[u] = __ldg(W + (k + 8 + u) * Ff + f);
        }
#pragma unroll
        for (int r = 0; r < 16; ++r) {
            const float* xr = &hsm[(rq * 16 + r) * 132 + k];
            float4 x0 = *(const float4*)xr;
            float4 x1 = *(const float4*)(xr + 4);
            acc[r] = fmaf(x0.x, w[0], acc[r]);
            acc[r] = fmaf(x0.y, w[1], acc[r]);
            acc[r] = fmaf(x0.z, w[2], acc[r]);
            acc[r] = fmaf(x0.w, w[3], acc[r]);
            acc[r] = fmaf(x1.x, w[4], acc[r]);
            acc[r] = fmaf(x1.y, w[5], acc[r]);
            acc[r] = fmaf(x1.z, w[6], acc[r]);
            acc[r] = fmaf(x1.w, w[7], acc[r]);
        }
#pragma unroll
        for (int u = 0; u < 8; ++u) w[u] = wn[u];
    }
    __syncthreads();

#pragma unroll
    for (int r = 0; r < 16; ++r) {
        int row = rq * 16 + r;
        hsm[row * 132 + f] = acc[r];
        g_hb[(size_t)(i0 + row) * Ff + f] = __float2half(acc[r]);
    }
    __syncthreads();

    int row = tid >> 3, c = tid & 7;
    float p1 = 0.f, p2 = 0.f;
#pragma unroll
    for (int i = 0; i < 16; ++i) {
        float hv = hsm[row * 132 + c * 16 + i];
        p1 = fmaf(hv, __ldg(a + c * 16 + i), p1);
        p2 = fmaf(hv, __ldg(a + Ff + c * 16 + i), p2);
    }
    p1 += __shfl_xor_sync(0xffffffffu, p1, 1);
    p1 += __shfl_xor_sync(0xffffffffu, p1, 2);
    p1 += __shfl_xor_sync(0xffffffffu, p1, 4);
    p2 += __shfl_xor_sync(0xffffffffu, p2, 1);
    p2 += __shfl_xor_sync(0xffffffffu, p2, 2);
    p2 += __shfl_xor_sync(0xffffffffu, p2, 4);
    if (c == 0) {
        float sd = p2 * LOG2E;
        g_ssrc[i0 + row] = p1 * LOG2E;
        g_sdst[i0 + row] = sd;
        atomicMax(&g_smax_enc, enc_f(sd));
    }
}

// ---------------------------------------------------------------------------
// K_main: grid 256, 256 thr, warp tile m32 x n32, 2 CTAs/SM.
// adj read dense: each warp-LDG.128 = 2 full rows x 256B contiguous
// (4 cache lines / 4 wavefronts). Thread owns 4 j's in 4 fixed rows.
// ---------------------------------------------------------------------------
__device__ __forceinline__ void mma16816(float* d, const uint32_t* A,
                                         uint32_t b0, uint32_t b1) {
    asm volatile(
        "mma.sync.aligned.m16n8k16.row.col.f32.f16.f16.f32 "
        "{%0,%1,%2,%3}, {%4,%5,%6,%7}, {%8,%9}, {%0,%1,%2,%3};"
        : "+f"(d[0]), "+f"(d[1]), "+f"(d[2]), "+f"(d[3])
        : "r"(A[0]), "r"(A[1]), "r"(A[2]), "r"(A[3]), "r"(b0), "r"(b1));
}

#define QBUF_OFF 0
#define HBUF_OFF 16384
#define SDST_OFF 49152
#define SMEM_SZ  57344

__global__ void __launch_bounds__(256, 2) k_main(const int* __restrict__ adj) {
    extern __shared__ __align__(16) char smem[];
    char* qbuf = smem + QBUF_OFF;
    char* sdst_sm = smem + SDST_OFF;
    uint32_t qb32 = smem_u32(smem + QBUF_OFF);
    uint32_t hb32 = smem_u32(smem + HBUF_OFF);

    int tid = threadIdx.x, lane = tid & 31, wid = tid >> 5;
    int ws = wid & 1, ns = wid >> 1;
    int bid = blockIdx.x;
    int i0 = (bid >> 1) * 64;
    int jh = bid & 1;
    int joff = jh * 4096;

    // ---- stage this half's sdst fp32 -> fp16 smem (4096 values) ----
    {
        const float4* sp = (const float4*)(g_sdst + joff);
        uint2* dp = (uint2*)sdst_sm;
#pragma unroll
        for (int u = 0; u < 4; ++u) {
            float4 v = __ldg(sp + tid * 4 + u);
            __half2 h0 = __floats2half2_rn(v.x, v.y);
            __half2 h1 = __floats2half2_rn(v.z, v.w);
            dp[tid * 4 + u] = make_uint2(*(uint32_t*)&h0, *(uint32_t*)&h1);
        }
    }

    // ---- q constants: thread owns 4 j's (lj*4..lj*4+3) in 4 rows ----
    int hs = lane >> 4, lj = lane & 15;
    float S = dec_f(g_smax_enc);
    int qrows[4];
    __half2 sA2[4], nB2[4];
    uint32_t q_sts[4];
    const int4* ap[4];
#pragma unroll
    for (int u = 0; u < 4; ++u) {
        int r = wid * 8 + 2 * u + hs;
        qrows[u] = r;
        float sA = g_ssrc[i0 + r];
        float tAx = sA + S;
        float nB = -fmaxf(tAx, ALPHAv * tAx);
        sA2[u] = __floats2half2_rn(sA, sA);
        nB2[u] = __floats2half2_rn(nB, nB);
        q_sts[u] = (uint32_t)(r * 128 + (((lj >> 1) ^ (r & 7)) << 4) + (lj & 1) * 8);
        ap[u] = (const int4*)(adj + (size_t)(i0 + r) * Nn + joff + lj * 4);
    }
    __half2 c02 = __floats2half2_rn(ALPHAv, ALPHAv);
    float lacc[4] = {0.f, 0.f, 0.f, 0.f};

    // ---- H cp.async: 1 row, 4 chunks of 16B per thread ----
    int hrow = tid >> 2, hc = tid & 3;
    uint32_t h_sts[4];
#pragma unroll
    for (int u = 0; u < 4; ++u)
        h_sts[u] = (uint32_t)(hrow * 256 + (((hc * 4 + u) ^ (hrow & 7)) << 4));
    const char* hsrc_base = (const char*)g_hb + ((size_t)(joff + hrow) * Ff + hc * 32) * 2;

    // ---- mma addressing ----
    int lgroup = lane >> 3;
    int lrow_in = (lgroup & 1) * 8 + (lane & 7);
    int bchunk = ns * 4 + (lgroup >> 1);
    int arow = ws * 32 + (lane & 15);
    int arx = arow & 7;
    uint32_t a_base = (uint32_t)(arow * 128);
    int asel = lane >> 4;

    float acc[2][4][4];
#pragma unroll
    for (int mb = 0; mb < 2; ++mb)
#pragma unroll
        for (int nb = 0; nb < 4; ++nb)
#pragma unroll
            for (int k = 0; k < 4; ++k) acc[mb][nb][k] = 0.f;

    // ---- prologue: H(0) cp.async + adj(0) ----
#pragma unroll
    for (int u = 0; u < 4; ++u)
        asm volatile("cp.async.cg.shared.global [%0], [%1], 16;"
                     :: "r"(hb32 + h_sts[u]), "l"(hsrc_base + u * 16) : "memory");
    asm volatile("cp.async.commit_group;" ::: "memory");

    int4 av[4];
#pragma unroll
    for (int u = 0; u < 4; ++u) av[u] = __ldg(ap[u]);
    __syncthreads();  // sdst visible

    // ---- q(0) ----
    {
        uint2 sd = *(const uint2*)(sdst_sm + lj * 8);
        __half2 sd0 = *(__half2*)&sd.x, sd1 = *(__half2*)&sd.y;
#pragma unroll
        for (int u = 0; u < 4; ++u) {
            __half2 t0 = __hadd2(sd0, sA2[u]);
            __half2 t1 = __hadd2(sd1, sA2[u]);
            __half2 m0 = __hadd2(__hmax2(t0, __hmul2(t0, c02)), nB2[u]);
            __half2 m1 = __hadd2(__hmax2(t1, __hmul2(t1, c02)), nB2[u]);
            uint32_t e0 = hexp2(*(uint32_t*)&m0);
            uint32_t e1 = hexp2(*(uint32_t*)&m1);
            uint32_t k0 = (av[u].x > 0 ? 0x3C00u : 0u) | (av[u].y > 0 ? 0x3C000000u : 0u);
            uint32_t k1 = (av[u].z > 0 ? 0x3C00u : 0u) | (av[u].w > 0 ? 0x3C000000u : 0u);
            __half2 q0 = __hmul2(*(__half2*)&e0, *(__half2*)&k0);
            __half2 q1 = __hmul2(*(__half2*)&e1, *(__half2*)&k1);
            float2 f0 = __half22float2(__hadd2(q0, q1));
            lacc[u] += f0.x + f0.y;
            *(uint2*)(qbuf + q_sts[u]) = make_uint2(*(uint32_t*)&q0, *(uint32_t*)&q1);
        }
    }
    asm volatile("cp.async.wait_group 0;" ::: "memory");
    __syncthreads();  // q(0), H(0) visible

    for (int t = 0; t < 64; ++t) {
        // ---- issue H(t+1) cp.async + adj(t+1) LDGs ----
        if (t < 63) {
            int tt = t + 1;
            uint32_t dst = hb32 + (tt & 1) * 16384;
            const char* src = hsrc_base + (size_t)tt * 64 * 256;
#pragma unroll
            for (int u = 0; u < 4; ++u)
                asm volatile("cp.async.cg.shared.global [%0], [%1], 16;"
                             :: "r"(dst + h_sts[u]), "l"(src + u * 16) : "memory");
            asm volatile("cp.async.commit_group;" ::: "memory");
#pragma unroll
            for (int u = 0; u < 4; ++u) av[u] = __ldg(ap[u] + tt * 16);
        }

        // ---- MMA on tile t ----
        uint32_t qb = qb32 + (uint32_t)((t & 1) * 8192);
        uint32_t hb = hb32 + (uint32_t)((t & 1) * 16384);
#pragma unroll
        for (int kb = 0; kb < 4; ++kb) {
            uint32_t a0[4], a1[4];
            uint32_t aaddr = qb + a_base + (uint32_t)((((2 * kb + asel) ^ arx)) << 4);
            asm volatile(
                "ldmatrix.sync.aligned.m8n8.x4.shared.b16 {%0,%1,%2,%3}, [%4];"
                : "=r"(a0[0]), "=r"(a0[1]), "=r"(a0[2]), "=r"(a0[3]) : "r"(aaddr));
            asm volatile(
                "ldmatrix.sync.aligned.m8n8.x4.shared.b16 {%0,%1,%2,%3}, [%4];"
                : "=r"(a1[0]), "=r"(a1[1]), "=r"(a1[2]), "=r"(a1[3])
                : "r"(aaddr + 2048));
            int lrow = kb * 16 + lrow_in;
            int rx = lrow & 7;
            uint32_t rowa = hb + (uint32_t)(lrow * 256);
#pragma unroll
            for (int p = 0; p < 2; ++p) {
                uint32_t baddr = rowa + (uint32_t)((((bchunk + 2 * p) ^ rx)) << 4);
                uint32_t b0, b1, b2, b3;
                asm volatile(
                    "ldmatrix.sync.aligned.m8n8.x4.trans.shared.b16 "
                    "{%0,%1,%2,%3}, [%4];"
                    : "=r"(b0), "=r"(b1), "=r"(b2), "=r"(b3) : "r"(baddr));
                mma16816(acc[0][2 * p], a0, b0, b1);
                mma16816(acc[0][2 * p + 1], a0, b2, b3);
                mma16816(acc[1][2 * p], a1, b0, b1);
                mma16816(acc[1][2 * p + 1], a1, b2, b3);
            }
        }

        // ---- compute q(t+1), STS into other buffer ----
        if (t < 63) {
            int tt = t + 1;
            char* qd = qbuf + (tt & 1) * 8192;
            uint2 sd = *(const uint2*)(sdst_sm + tt * 128 + lj * 8);
            __half2 sd0 = *(__half2*)&sd.x, sd1 = *(__half2*)&sd.y;
#pragma unroll
            for (int u = 0; u < 4; ++u) {
                __half2 t0 = __hadd2(sd0, sA2[u]);
                __half2 t1 = __hadd2(sd1, sA2[u]);
                __half2 m0 = __hadd2(__hmax2(t0, __hmul2(t0, c02)), nB2[u]);
                __half2 m1 = __hadd2(__hmax2(t1, __hmul2(t1, c02)), nB2[u]);
                uint32_t e0 = hexp2(*(uint32_t*)&m0);
                uint32_t e1 = hexp2(*(uint32_t*)&m1);
                uint32_t k0 = (av[u].x > 0 ? 0x3C00u : 0u) | (av[u].y > 0 ? 0x3C000000u : 0u);
                uint32_t k1 = (av[u].z > 0 ? 0x3C00u : 0u) | (av[u].w > 0 ? 0x3C000000u : 0u);
                __half2 q0 = __hmul2(*(__half2*)&e0, *(__half2*)&k0);
                __half2 q1 = __hmul2(*(__half2*)&e1, *(__half2*)&k1);
                float2 f0 = __half22float2(__hadd2(q0, q1));
                lacc[u] += f0.x + f0.y;
                *(uint2*)(qd + q_sts[u]) = make_uint2(*(uint32_t*)&q0, *(uint32_t*)&q1);
            }
            asm volatile("cp.async.wait_group 0;" ::: "memory");
        }
        __syncthreads();
    }

    // ---- partial l: reduce over 16 lanes sharing each row ----
#pragma unroll
    for (int u = 0; u < 4; ++u) {
        lacc[u] += __shfl_xor_sync(0xffffffffu, lacc[u], 1);
        lacc[u] += __shfl_xor_sync(0xffffffffu, lacc[u], 2);
        lacc[u] += __shfl_xor_sync(0xffffffffu, lacc[u], 4);
        lacc[u] += __shfl_xor_sync(0xffffffffu, lacc[u], 8);
    }
    if (lj == 0) {
#pragma unroll
        for (int u = 0; u < 4; ++u)
            g_lpart[jh * Nn + i0 + qrows[u]] = lacc[u];
    }

    // ---- write unnormalized partials ----
    int g = lane >> 2, c = lane & 3;
    float* pb = g_part + (size_t)jh * Nn * Ff;
#pragma unroll
    for (int mb = 0; mb < 2; ++mb) {
        int rA = ws * 32 + mb * 16 + g, rB = rA + 8;
#pragma unroll
        for (int nb = 0; nb < 4; ++nb) {
            int col = ns * 32 + nb * 8 + 2 * c;
            *(float2*)(pb + (size_t)(i0 + rA) * Ff + col) =
                make_float2(acc[mb][nb][0], acc[mb][nb][1]);
            *(float2*)(pb + (size_t)(i0 + rB) * Ff + col) =
                make_float2(acc[mb][nb][2], acc[mb][nb][3]);
        }
    }
}

// ---------------------------------------------------------------------------
// K_combine: out = (p0 + p1) / (l0 + l1), float4 per thread
// ---------------------------------------------------------------------------
__global__ void __launch_bounds__(256) k_combine(float* __restrict__ out) {
    int idx4 = blockIdx.x * 256 + threadIdx.x;
    int row = idx4 >> 5;  // 32 float4 per row
    float il = 1.0f / (g_lpart[row] + g_lpart[Nn + row]);
    const float4* p0 = (const float4*)g_part;
    const float4* p1 = (const float4*)(g_part + (size_t)Nn * Ff);
    float4 a = p0[idx4], b = p1[idx4];
    float4 o;
    o.x = (a.x + b.x) * il;
    o.y = (a.y + b.y) * il;
    o.z = (a.z + b.z) * il;
    o.w = (a.w + b.w) * il;
    ((float4*)out)[idx4] = o;
}

// ---------------------------------------------------------------------------
extern "C" void kernel_launch(void* const* d_in, const int* in_sizes, int n_in,
                              void* d_out, int out_size) {
    const float* x   = (const float*)d_in[0];
    const int*   adj = (const int*)d_in[1];
    const float* W   = (const float*)d_in[2];
    const float* a   = (const float*)d_in[3];
    float* out = (float*)d_out;

    cudaFuncSetAttribute(k_main, cudaFuncAttributeMaxDynamicSharedMemorySize, SMEM_SZ);

    k_init<<<1, 1>>>();
    k_xw<<<Nn / 64, 512>>>(x, W, a);
    k_main<<<Nn / 64 * 2, 256, SMEM_SZ>>>(adj);
    k_combine<<<Nn * Ff / 4 / 256, 256>>>(out);
}